// round 11
// baseline (speedup 1.0000x reference)
#include <cuda_runtime.h>
#include <cuda_bf16.h>
#include <math.h>
#include <stdint.h>

#define BATCH   2
#define SEQ     2048
#define DMODEL  2048
#define NHEADS  32
#define DSTATE  64
#define HEADDIM 64
#define DCONV   4
#define INTERSZ 5504
#define DINNER  DMODEL
#define CONVDIM (DINNER + 2*NHEADS*DSTATE)              /* 6144 */
#define DPROJ   (2*DINNER + 2*NHEADS*DSTATE + NHEADS)   /* 8224 */
#define MROWS   (BATCH*SEQ)                             /* 4096 */

// ---------------- scratch ----------------
__device__ float g_zx   [(size_t)MROWS * DPROJ];
__device__ float g_res2 [(size_t)MROWS * DMODEL];
__device__ float g_guf  [(size_t)MROWS * 11008];
// packed bf16 hi/lo tile images: tile = 128 rows x 32 cols, 64B rows, XOR swizzle.
// hi plane 8192B + lo plane 8192B = 16384B per tile.
#define PB_I 0
#define PB_O (65*64)
#define PB_G (PB_O + 16*64)
#define PB_U (PB_G + 43*64)
#define PB_D (PB_U + 43*64)
#define PB_TILES (PB_D + 16*172)
__device__ __align__(128) uint8_t g_pa[(size_t)32 * 172 * 16384];     /* 90 MB  */
__device__ __align__(128) uint8_t g_pb[(size_t)PB_TILES * 16384];     /* 220 MB */

static __device__ __forceinline__ uint32_t smem_u32(const void* p) {
    uint32_t a;
    asm("{ .reg .u64 t; cvta.to.shared.u64 t, %1; cvt.u32.u64 %0, t; }" : "=r"(a) : "l"(p));
    return a;
}

#define LDSM_X4(r, addr) \
    asm volatile("ldmatrix.sync.aligned.m8n8.x4.shared.b16 {%0,%1,%2,%3}, [%4];" \
        : "=r"((r)[0]), "=r"((r)[1]), "=r"((r)[2]), "=r"((r)[3]) : "r"(addr))

#define MMA16816(c, a, b0, b1) \
    asm volatile("mma.sync.aligned.m16n8k16.row.col.f32.bf16.bf16.f32 " \
        "{%0,%1,%2,%3}, {%4,%5,%6,%7}, {%8,%9}, {%0,%1,%2,%3};" \
        : "+f"((c)[0]), "+f"((c)[1]), "+f"((c)[2]), "+f"((c)[3]) \
        : "r"((a)[0]), "r"((a)[1]), "r"((a)[2]), "r"((a)[3]), "r"(b0), "r"(b1))

#define CPASYNC16(dst, src) \
    asm volatile("cp.async.cg.shared.global [%0], [%1], 16;" :: "r"(dst), "l"(src))

static __device__ __forceinline__ void cvt8u(const float* v, uint32_t* hi, uint32_t* lo) {
#pragma unroll
    for (int j = 0; j < 4; j++) {
        __nv_bfloat162 h = __float22bfloat162_rn(make_float2(v[2*j], v[2*j+1]));
        float g0 = __bfloat162float(h.x), g1 = __bfloat162float(h.y);
        __nv_bfloat162 l = __float22bfloat162_rn(make_float2(v[2*j]-g0, v[2*j+1]-g1));
        hi[j] = *(uint32_t*)&h; lo[j] = *(uint32_t*)&l;
    }
}

// swizzled byte offset within an 8KB plane for (row, c16)
static __device__ __forceinline__ uint32_t swz(int r, int c) {
    return (uint32_t)(r * 64 + ((c ^ ((r >> 1) & 3)) << 4));
}

// ---------------- pack: fp32 -> bf16 hi/lo swizzled 128x32 tiles ----------------
__global__ void pack_tiles(const float* __restrict__ src, uint8_t* __restrict__ dst,
                           int K, int nslab, int Nreal, int nChunks)
{
    for (int id = blockIdx.x * blockDim.x + threadIdx.x; id < nChunks;
         id += gridDim.x * blockDim.x) {
        const int tile = id >> 9;
        const int w = id & 511;
        const int r = w >> 2, c = w & 3;
        const int mt = tile / nslab;
        const int s  = tile - mt * nslab;
        const int row = mt * 128 + r;
        float v[8] = {0.f,0.f,0.f,0.f,0.f,0.f,0.f,0.f};
        if (row < Nreal) {
            const float* p = src + (size_t)row * K + s * 32 + c * 8;
            *(float4*)&v[0] = *(const float4*)p;
            *(float4*)&v[4] = *(const float4*)(p + 4);
        }
        uint32_t hi[4], lo[4];
        cvt8u(v, hi, lo);
        uint8_t* base = dst + (size_t)tile * 16384 + swz(r, c);
        *(uint4*)base           = *(uint4*)hi;
        *(uint4*)(base + 8192)  = *(uint4*)lo;
    }
}

// ---------------- fused silu(gate)*up -> packed A tiles for down GEMM ----------------
__global__ void pack_silu(const float* __restrict__ guf, uint8_t* __restrict__ dst,
                          int nChunks)
{
    for (int id = blockIdx.x * blockDim.x + threadIdx.x; id < nChunks;
         id += gridDim.x * blockDim.x) {
        const int tile = id >> 9;
        const int w = id & 511;
        const int r = w >> 2, c = w & 3;
        const int mt = tile / 172;
        const int s  = tile - mt * 172;
        const int row = mt * 128 + r;
        const float* p = guf + (size_t)row * 11008 + s * 32 + c * 8;
        float vg[8], vu[8], v[8];
        *(float4*)&vg[0] = *(const float4*)p;
        *(float4*)&vg[4] = *(const float4*)(p + 4);
        *(float4*)&vu[0] = *(const float4*)(p + INTERSZ);
        *(float4*)&vu[4] = *(const float4*)(p + INTERSZ + 4);
#pragma unroll
        for (int j = 0; j < 8; j++)
            v[j] = vu[j] * vg[j] / (1.f + expf(-vg[j]));
        uint32_t hi[4], lo[4];
        cvt8u(v, hi, lo);
        uint8_t* base = dst + (size_t)tile * 16384 + swz(r, c);
        *(uint4*)base           = *(uint4*)hi;
        *(uint4*)(base + 8192)  = *(uint4*)lo;
    }
}

// ---------------- fused RMSNorm (optionally * mask) -> packed A tiles ----------------
__global__ __launch_bounds__(256) void rmsnorm_pack(const float* __restrict__ x,
                                                    const float* __restrict__ w,
                                                    const float* __restrict__ mask,
                                                    uint8_t* __restrict__ dst)
{
    const int m = blockIdx.x;
    const int t = threadIdx.x;
    const float* row = x + (size_t)m * DMODEL;
    float v[8];
    *(float4*)&v[0] = *(const float4*)(row + t * 8);
    *(float4*)&v[4] = *(const float4*)(row + t * 8 + 4);
    float s = 0.f;
#pragma unroll
    for (int j = 0; j < 8; j++) s += v[j] * v[j];
#pragma unroll
    for (int o = 16; o > 0; o >>= 1) s += __shfl_xor_sync(0xffffffffu, s, o);
    __shared__ float red[8];
    const int lane = t & 31, wid = t >> 5;
    if (lane == 0) red[wid] = s;
    __syncthreads();
    if (wid == 0) {
        s = (lane < 8) ? red[lane] : 0.f;
#pragma unroll
        for (int o = 4; o > 0; o >>= 1) s += __shfl_xor_sync(0xffffffffu, s, o);
        if (lane == 0) red[0] = s;
    }
    __syncthreads();
    const float inv = rsqrtf(red[0] * (1.0f / (float)DMODEL) + 1e-6f) *
                      (mask ? mask[m] : 1.f);
    float wv[8];
    *(float4*)&wv[0] = *(const float4*)(w + t * 8);
    *(float4*)&wv[4] = *(const float4*)(w + t * 8 + 4);
#pragma unroll
    for (int j = 0; j < 8; j++) v[j] = v[j] * inv * wv[j];
    uint32_t hi[4], lo[4];
    cvt8u(v, hi, lo);
    const int st = t >> 2, c = t & 3, r = m & 127;
    uint8_t* base = dst + (size_t)((m >> 7) * 64 + st) * 16384 + swz(r, c);
    *(uint4*)base          = *(uint4*)hi;
    *(uint4*)(base + 8192) = *(uint4*)lo;
}

// ====== bf16x3 GEMM, swizzled packed operands, 3-stage K32 cp.async ======
#define OFF_AL 8192
#define OFF_BH 16384
#define OFF_BL 24576
#define STG    32768
#define GSMEM  (3*STG)

__global__ __launch_bounds__(256, 2) void gemm_mma(
    const uint8_t* __restrict__ Ap, const uint8_t* __restrict__ Bp,
    float* __restrict__ C, const float* __restrict__ addv,
    int N, int nslab, int addflag)
{
    extern __shared__ char sm[];
    const int tid  = threadIdx.x;
    const int warp = tid >> 5, lane = tid & 31;
    const int wm = warp >> 2, wn = warp & 3;       // 2 x 4 warps, warp tile 64x32
    const uint32_t sbase = smem_u32(sm);

    const uint8_t* aT = Ap + (size_t)blockIdx.x * nslab * 16384;
    const uint8_t* bT = Bp + (size_t)blockIdx.y * nslab * 16384;

    float acc[4][4][4];
#pragma unroll
    for (int i = 0; i < 4; i++)
#pragma unroll
        for (int j = 0; j < 4; j++)
#pragma unroll
            for (int r = 0; r < 4; r++) acc[i][j][r] = 0.f;

    // prologue: stages 0 and 1
#pragma unroll
    for (int ss = 0; ss < 2; ss++) {
        const uint32_t d = sbase + (uint32_t)ss * STG;
        const size_t o = (size_t)ss * 16384;
#pragma unroll
        for (int j = 0; j < 4; j++) {
            const uint32_t cid = (uint32_t)tid * 16 + (uint32_t)j * 4096;
            CPASYNC16(d + cid,         aT + o + cid);
            CPASYNC16(d + 16384 + cid, bT + o + cid);
        }
        asm volatile("cp.async.commit_group;" ::: "memory");
    }

    const int lrow  = lane & 15;
    const int lcsel = lane >> 4;

    int cur = 0;
    for (int s = 0; s < nslab; s++) {
        if (s + 1 < nslab) { asm volatile("cp.async.wait_group 1;" ::: "memory"); }
        else               { asm volatile("cp.async.wait_group 0;" ::: "memory"); }
        __syncthreads();

        if (s + 2 < nslab) {
            int nx2 = cur + 2; if (nx2 >= 3) nx2 -= 3;
            const uint32_t d = sbase + (uint32_t)nx2 * STG;
            const size_t o = (size_t)(s + 2) * 16384;
#pragma unroll
            for (int j = 0; j < 4; j++) {
                const uint32_t cid = (uint32_t)tid * 16 + (uint32_t)j * 4096;
                CPASYNC16(d + cid,         aT + o + cid);
                CPASYNC16(d + 16384 + cid, bT + o + cid);
            }
            asm volatile("cp.async.commit_group;" ::: "memory");
        }

        const uint32_t stb = sbase + (uint32_t)cur * STG;
#pragma unroll
        for (int ks = 0; ks < 2; ks++) {
            const int kc = ks * 2 + lcsel;
            uint32_t bh[2][4], bl[2][4];
#pragma unroll
            for (int bt = 0; bt < 2; bt++) {
                const uint32_t off = swz(wn*32 + bt*16 + lrow, kc);
                LDSM_X4(bh[bt], stb + OFF_BH + off);
                LDSM_X4(bl[bt], stb + OFF_BL + off);
            }
#pragma unroll
            for (int mt = 0; mt < 4; mt++) {
                uint32_t ah[4], al[4];
                const uint32_t off = swz(wm*64 + mt*16 + lrow, kc);
                LDSM_X4(ah, stb + off);
                LDSM_X4(al, stb + OFF_AL + off);
#pragma unroll
                for (int nt = 0; nt < 4; nt++) {
                    const int bt = nt >> 1, sel = nt & 1;
                    const uint32_t b0h = bh[bt][sel], b1h = bh[bt][2+sel];
                    const uint32_t b0l = bl[bt][sel], b1l = bl[bt][2+sel];
                    MMA16816(acc[mt][nt], ah, b0h, b1h);
                    MMA16816(acc[mt][nt], al, b0h, b1h);
                    MMA16816(acc[mt][nt], ah, b0l, b1l);
                }
            }
        }
        if (++cur == 3) cur = 0;
    }

    // ---- epilogue ----
    const int g  = lane >> 2;
    const int t4 = lane & 3;
    const int bm = blockIdx.x * 128, bn = blockIdx.y * 128;
#pragma unroll
    for (int mt = 0; mt < 4; mt++) {
        const int row = bm + wm*64 + mt*16 + g;
#pragma unroll
        for (int nt = 0; nt < 4; nt++) {
            const int col = bn + wn*32 + nt*8 + t4*2;
            if (col < N) {
                float2 v0 = make_float2(acc[mt][nt][0], acc[mt][nt][1]);
                float2 v1 = make_float2(acc[mt][nt][2], acc[mt][nt][3]);
                const size_t i0 = (size_t)row * N + col;
                const size_t i1 = (size_t)(row + 8) * N + col;
                if (addflag) {
                    const float2 a0 = *(const float2*)(addv + i0);
                    const float2 a1 = *(const float2*)(addv + i1);
                    v0.x += a0.x; v0.y += a0.y; v1.x += a1.x; v1.y += a1.y;
                }
                *(float2*)(C + i0) = v0;
                *(float2*)(C + i1) = v1;
            }
        }
    }
}

// ---- SSM scan with FUSED causal conv (from zx) and packed bf16 output ----
// per-buffer smem layout (floats): x[8][64] | B[8][64] | C[8][64] | z[8][64] | a[8]
#define CHK 8
#define SBUF 2064
__global__ __launch_bounds__(256) void scan_kernel(
    const float* __restrict__ zx, const float* __restrict__ cw,
    const float* __restrict__ cb, const float* __restrict__ Dv,
    const float* __restrict__ zb, uint8_t* __restrict__ pa_out)
{
    const int bh = blockIdx.x;
    const int b = bh >> 5;
    const int h = bh & 31;
    const int tid = threadIdx.x;
    const int p = tid >> 2;
    const int q = tid & 3;
    const int n0 = q << 4;

    __shared__ __align__(16) float sd[2][SBUF];

    // loader setup: 9 elements per thread
    int lts[9], lcol[9], lkind[9], lsh[9];
    float cwx[9], cwy[9], cwz[9], cww[9], cbv[9];
    bool lvalid[9];
#pragma unroll
    for (int k = 0; k < 9; k++) {
        const int e = tid + k * 256;
        lvalid[k] = (e < CHK * 257);
        const int tsub = e / 257;
        const int j = e - tsub * 257;
        lts[k] = tsub;
        int c = 0;
        if (j < 192) {
            lkind[k] = 0;
            if (j < 64)       c = h * HEADDIM + j;
            else if (j < 128) c = DINNER + h * DSTATE + (j - 64);
            else              c = DINNER + NHEADS * DSTATE + h * DSTATE + (j - 128);
            lcol[k] = DINNER + c;     // zx column for conv input
            lsh[k]  = (j < 64) ? (tsub*64 + j)
                    : (j < 128) ? (512 + tsub*64 + (j-64))
                                : (1024 + tsub*64 + (j-128));
            if (lvalid[k]) {
                const float4 w4 = *(const float4*)(cw + (size_t)c * DCONV);
                cwx[k] = w4.x; cwy[k] = w4.y; cwz[k] = w4.z; cww[k] = w4.w;
                cbv[k] = cb[c];
            }
        } else if (j < 256) {
            lkind[k] = 1; lcol[k] = h * HEADDIM + (j - 192);
            lsh[k] = 1536 + tsub*64 + (j-192);
        } else {
            lkind[k] = 2; lcol[k] = 2*DINNER + 2*NHEADS*DSTATE + h;
            lsh[k] = 2048 + tsub;
        }
    }

    // element loader for chunk cidx
    auto loadv = [&](int k, int cidx) -> float {
        const int t = cidx * CHK + lts[k];
        const size_t mrow = (size_t)b * SEQ + t;
        if (lkind[k] == 0) {
            float acc = cbv[k];
            const float* zp = zx + (mrow - 3) * DPROJ + lcol[k];
            if (t >= 3) {
                acc = fmaf(cwx[k], zp[0],         acc);
                acc = fmaf(cwy[k], zp[DPROJ],     acc);
                acc = fmaf(cwz[k], zp[2*DPROJ],   acc);
                acc = fmaf(cww[k], zp[3*DPROJ],   acc);
            } else {
                if (t >= 3) acc = fmaf(cwx[k], zp[0],       acc);
                if (t >= 2) acc = fmaf(cwy[k], zp[DPROJ],   acc);
                if (t >= 1) acc = fmaf(cwz[k], zp[2*DPROJ], acc);
                acc = fmaf(cww[k], zp[3*DPROJ], acc);
            }
            return acc;
        } else if (lkind[k] == 1) {
            return zx[mrow * DPROJ + lcol[k]];
        } else {
            const float v = zx[mrow * DPROJ + lcol[k]];
            return 1.f / (1.f + expf(v));
        }
    };

    // prologue: chunk 0
#pragma unroll
    for (int k = 0; k < 9; k++)
        if (lvalid[k]) sd[0][lsh[k]] = loadv(k, 0);
    __syncthreads();

    float st[16];
#pragma unroll
    for (int i = 0; i < 16; i++) st[i] = 0.f;
    const float Dh = Dv[h];
    const float zbias = zb[h * HEADDIM + p];

    // output packing constants (q==0 threads write col = h*64+p)
    const int ocol = h * HEADDIM + p;
    const int oslab = ocol >> 5;
    const int oc16 = (ocol >> 3) & 3;
    const int oin = (ocol & 7) * 2;
    uint8_t* obase0 = pa_out + ((size_t)(b * 16) * 64 + oslab) * 16384;

    const int NC = SEQ / CHK;
    for (int c = 0; c < NC; c++) {
        const int cur = c & 1;
        const bool pre = (c + 1 < NC);
        float regv[9];
        if (pre) {
#pragma unroll
            for (int k = 0; k < 9; k++)
                if (lvalid[k]) regv[k] = loadv(k, c + 1);
        }
        const float* sb = sd[cur];
#pragma unroll
        for (int tsub = 0; tsub < CHK; tsub++) {
            const float a  = sb[2048 + tsub];
            const float xv = sb[tsub*64 + p];
            const float4* Bp4 = (const float4*)(sb + 512 + tsub*64 + n0);
            const float4* Cp4 = (const float4*)(sb + 1024 + tsub*64 + n0);
            float Bv[16], Cv[16];
            *(float4*)&Bv[0]  = Bp4[0]; *(float4*)&Bv[4]  = Bp4[1];
            *(float4*)&Bv[8]  = Bp4[2]; *(float4*)&Bv[12] = Bp4[3];
            *(float4*)&Cv[0]  = Cp4[0]; *(float4*)&Cv[4]  = Cp4[1];
            *(float4*)&Cv[8]  = Cp4[2]; *(float4*)&Cv[12] = Cp4[3];
            float y = 0.f;
#pragma unroll
            for (int i = 0; i < 16; i++) {
                st[i] = a * st[i] + xv * Bv[i];
                y = fmaf(st[i], Cv[i], y);
            }
            y += __shfl_xor_sync(0xffffffffu, y, 1);
            y += __shfl_xor_sync(0xffffffffu, y, 2);
            if (q == 0) {
                const int t = c * CHK + tsub;
                const float zval = sb[1536 + tsub*64 + p] + zbias;
                const float sig = 1.f / (1.f + expf(-zval));
                const float v = (y + Dh * xv) * (zval * sig);
                const __nv_bfloat16 hb = __float2bfloat16(v);
                const __nv_bfloat16 lb = __float2bfloat16(v - __bfloat162float(hb));
                uint8_t* base = obase0 + (size_t)(t >> 7) * (64 * 16384)
                                + swz(t & 127, oc16) + oin;
                *(__nv_bfloat16*)base          = hb;
                *(__nv_bfloat16*)(base + 8192) = lb;
            }
        }
        if (pre) {
#pragma unroll
            for (int k = 0; k < 9; k++)
                if (lvalid[k]) sd[cur ^ 1][lsh[k]] = regv[k];
        }
        __syncthreads();
    }
}

// ---------------- launcher ----------------
extern "C" void kernel_launch(void* const* d_in, const int* in_sizes, int n_in,
                              void* d_out, int out_size)
{
    (void)in_sizes; (void)n_in; (void)out_size;
    const float* hidden     = (const float*)d_in[0];
    const float* mask       = (const float*)d_in[1];
    const float* in_proj_w  = (const float*)d_in[2];
    const float* conv_w     = (const float*)d_in[3];
    const float* conv_b     = (const float*)d_in[4];
    const float* z_bias     = (const float*)d_in[5];
    const float* Dv         = (const float*)d_in[6];
    const float* out_proj_w = (const float*)d_in[7];
    const float* ln1_w      = (const float*)d_in[8];
    const float* ln2_w      = (const float*)d_in[9];
    const float* gate_w     = (const float*)d_in[10];
    const float* up_w       = (const float*)d_in[11];
    const float* down_w     = (const float*)d_in[12];
    float* out = (float*)d_out;

    float *zx, *res2, *guf;
    uint8_t *pa, *pb;
    cudaGetSymbolAddress((void**)&zx,    g_zx);
    cudaGetSymbolAddress((void**)&res2,  g_res2);
    cudaGetSymbolAddress((void**)&guf,   g_guf);
    cudaGetSymbolAddress((void**)&pa,    g_pa);
    cudaGetSymbolAddress((void**)&pb,    g_pb);

    uint8_t* pbI = pb + (size_t)PB_I * 16384;
    uint8_t* pbO = pb + (size_t)PB_O * 16384;
    uint8_t* pbG = pb + (size_t)PB_G * 16384;
    uint8_t* pbD = pb + (size_t)PB_D * 16384;

    cudaFuncSetAttribute(gemm_mma, cudaFuncAttributeMaxDynamicSharedMemorySize, GSMEM);
    const int PKG = 4096;

    // side stream for weight packs (overlap with main chain)
    cudaStream_t s2;
    cudaStreamCreateWithFlags(&s2, cudaStreamNonBlocking);
    cudaEvent_t evF, evI, evO, evGU, evD;
    cudaEventCreateWithFlags(&evF,  cudaEventDisableTiming);
    cudaEventCreateWithFlags(&evI,  cudaEventDisableTiming);
    cudaEventCreateWithFlags(&evO,  cudaEventDisableTiming);
    cudaEventCreateWithFlags(&evGU, cudaEventDisableTiming);
    cudaEventCreateWithFlags(&evD,  cudaEventDisableTiming);

    cudaEventRecord(evF, 0);
    cudaStreamWaitEvent(s2, evF, 0);
    pack_tiles<<<PKG, 256, 0, s2>>>(in_proj_w, pbI, 2048, 64, DPROJ, 65*64*512);
    cudaEventRecord(evI, s2);
    pack_tiles<<<PKG, 256, 0, s2>>>(out_proj_w, pbO, 2048, 64, DMODEL, 16*64*512);
    cudaEventRecord(evO, s2);
    pack_tiles<<<PKG, 256, 0, s2>>>(gate_w, pbG, 2048, 64, INTERSZ, 43*64*512);
    pack_tiles<<<PKG, 256, 0, s2>>>(up_w, pbG + (size_t)43*64*16384, 2048, 64, INTERSZ, 43*64*512);
    cudaEventRecord(evGU, s2);
    pack_tiles<<<PKG, 256, 0, s2>>>(down_w, pbD, 5504, 172, DMODEL, 16*172*512);
    cudaEventRecord(evD, s2);

    // ---- main chain ----
    rmsnorm_pack<<<MROWS, 256>>>(hidden, ln1_w, mask, pa);
    cudaStreamWaitEvent(0, evI, 0);
    gemm_mma<<<dim3(32, 65), 256, GSMEM>>>(pa, pbI, zx, nullptr, DPROJ, 64, 0);

    // fused conv + scan + gating + packed bf16 output (writes pa)
    scan_kernel<<<BATCH * NHEADS, 256>>>(zx, conv_w, conv_b, Dv, z_bias, pa);

    cudaStreamWaitEvent(0, evO, 0);
    gemm_mma<<<dim3(32, 16), 256, GSMEM>>>(pa, pbO, res2, hidden, DMODEL, 64, 1);

    // ---- MLP ----
    rmsnorm_pack<<<MROWS, 256>>>(res2, ln2_w, nullptr, pa);
    cudaStreamWaitEvent(0, evGU, 0);
    gemm_mma<<<dim3(32, 86), 256, GSMEM>>>(pa, pbG, guf, nullptr, 11008, 64, 0);

    pack_silu<<<PKG, 256>>>(guf, pa, 32*172*512);
    cudaStreamWaitEvent(0, evD, 0);
    gemm_mma<<<dim3(32, 16), 256, GSMEM>>>(pa, pbD, out, res2, DMODEL, 172, 1);
}

// round 12
// speedup vs baseline: 1.0885x; 1.0885x over previous
#include <cuda_runtime.h>
#include <cuda_bf16.h>
#include <math.h>
#include <stdint.h>

#define BATCH   2
#define SEQ     2048
#define DMODEL  2048
#define NHEADS  32
#define DSTATE  64
#define HEADDIM 64
#define DCONV   4
#define INTERSZ 5504
#define DINNER  DMODEL
#define CONVDIM (DINNER + 2*NHEADS*DSTATE)              /* 6144 */
#define DPROJ   (2*DINNER + 2*NHEADS*DSTATE + NHEADS)   /* 8224 */
#define MROWS   (BATCH*SEQ)                             /* 4096 */

// ---------------- scratch ----------------
__device__ float g_zx   [(size_t)MROWS * DPROJ];
__device__ float g_xbc  [(size_t)MROWS * CONVDIM];
__device__ float g_gated[(size_t)MROWS * DMODEL];
__device__ float g_res2 [(size_t)MROWS * DMODEL];
__device__ float g_guf  [(size_t)MROWS * 11008];
#define PB_I 0
#define PB_O (65*64)
#define PB_G (PB_O + 16*64)
#define PB_U (PB_G + 43*64)
#define PB_D (PB_U + 43*64)
#define PB_TILES (PB_D + 16*172)
__device__ __align__(128) uint8_t g_pa[(size_t)32 * 172 * 16384];     /* 90 MB  */
__device__ __align__(128) uint8_t g_pb[(size_t)PB_TILES * 16384];     /* 220 MB */

static __device__ __forceinline__ uint32_t smem_u32(const void* p) {
    uint32_t a;
    asm("{ .reg .u64 t; cvta.to.shared.u64 t, %1; cvt.u32.u64 %0, t; }" : "=r"(a) : "l"(p));
    return a;
}

#define LDSM_X4(r, addr) \
    asm volatile("ldmatrix.sync.aligned.m8n8.x4.shared.b16 {%0,%1,%2,%3}, [%4];" \
        : "=r"((r)[0]), "=r"((r)[1]), "=r"((r)[2]), "=r"((r)[3]) : "r"(addr))

#define MMA16816(c, a, b0, b1) \
    asm volatile("mma.sync.aligned.m16n8k16.row.col.f32.bf16.bf16.f32 " \
        "{%0,%1,%2,%3}, {%4,%5,%6,%7}, {%8,%9}, {%0,%1,%2,%3};" \
        : "+f"((c)[0]), "+f"((c)[1]), "+f"((c)[2]), "+f"((c)[3]) \
        : "r"((a)[0]), "r"((a)[1]), "r"((a)[2]), "r"((a)[3]), "r"(b0), "r"(b1))

#define CPASYNC16(dst, src) \
    asm volatile("cp.async.cg.shared.global [%0], [%1], 16;" :: "r"(dst), "l"(src))

static __device__ __forceinline__ void cvt8u(const float* v, uint32_t* hi, uint32_t* lo) {
#pragma unroll
    for (int j = 0; j < 4; j++) {
        __nv_bfloat162 h = __float22bfloat162_rn(make_float2(v[2*j], v[2*j+1]));
        float g0 = __bfloat162float(h.x), g1 = __bfloat162float(h.y);
        __nv_bfloat162 l = __float22bfloat162_rn(make_float2(v[2*j]-g0, v[2*j+1]-g1));
        hi[j] = *(uint32_t*)&h; lo[j] = *(uint32_t*)&l;
    }
}

static __device__ __forceinline__ uint32_t swz(int r, int c) {
    return (uint32_t)(r * 64 + ((c ^ ((r >> 1) & 3)) << 4));
}

// ---------------- pack: fp32 -> bf16 hi/lo swizzled 128x32 tiles ----------------
__global__ void pack_tiles(const float* __restrict__ src, uint8_t* __restrict__ dst,
                           int K, int nslab, int Nreal, int nChunks)
{
    for (int id = blockIdx.x * blockDim.x + threadIdx.x; id < nChunks;
         id += gridDim.x * blockDim.x) {
        const int tile = id >> 9;
        const int w = id & 511;
        const int r = w >> 2, c = w & 3;
        const int mt = tile / nslab;
        const int s  = tile - mt * nslab;
        const int row = mt * 128 + r;
        float v[8] = {0.f,0.f,0.f,0.f,0.f,0.f,0.f,0.f};
        if (row < Nreal) {
            const float* p = src + (size_t)row * K + s * 32 + c * 8;
            *(float4*)&v[0] = *(const float4*)p;
            *(float4*)&v[4] = *(const float4*)(p + 4);
        }
        uint32_t hi[4], lo[4];
        cvt8u(v, hi, lo);
        uint8_t* base = dst + (size_t)tile * 16384 + swz(r, c);
        *(uint4*)base           = *(uint4*)hi;
        *(uint4*)(base + 8192)  = *(uint4*)lo;
    }
}

// ---------------- fused silu(gate)*up -> packed A tiles for down GEMM ----------------
__global__ void pack_silu(const float* __restrict__ guf, uint8_t* __restrict__ dst,
                          int nChunks)
{
    for (int id = blockIdx.x * blockDim.x + threadIdx.x; id < nChunks;
         id += gridDim.x * blockDim.x) {
        const int tile = id >> 9;
        const int w = id & 511;
        const int r = w >> 2, c = w & 3;
        const int mt = tile / 172;
        const int s  = tile - mt * 172;
        const int row = mt * 128 + r;
        const float* p = guf + (size_t)row * 11008 + s * 32 + c * 8;
        float vg[8], vu[8], v[8];
        *(float4*)&vg[0] = *(const float4*)p;
        *(float4*)&vg[4] = *(const float4*)(p + 4);
        *(float4*)&vu[0] = *(const float4*)(p + INTERSZ);
        *(float4*)&vu[4] = *(const float4*)(p + INTERSZ + 4);
#pragma unroll
        for (int j = 0; j < 8; j++)
            v[j] = vu[j] * vg[j] / (1.f + expf(-vg[j]));
        uint32_t hi[4], lo[4];
        cvt8u(v, hi, lo);
        uint8_t* base = dst + (size_t)tile * 16384 + swz(r, c);
        *(uint4*)base           = *(uint4*)hi;
        *(uint4*)(base + 8192)  = *(uint4*)lo;
    }
}

// ---------------- fused RMSNorm (optionally * mask) -> packed A tiles ----------------
__global__ __launch_bounds__(256) void rmsnorm_pack(const float* __restrict__ x,
                                                    const float* __restrict__ w,
                                                    const float* __restrict__ mask,
                                                    uint8_t* __restrict__ dst)
{
    const int m = blockIdx.x;
    const int t = threadIdx.x;
    const float* row = x + (size_t)m * DMODEL;
    float v[8];
    *(float4*)&v[0] = *(const float4*)(row + t * 8);
    *(float4*)&v[4] = *(const float4*)(row + t * 8 + 4);
    float s = 0.f;
#pragma unroll
    for (int j = 0; j < 8; j++) s += v[j] * v[j];
#pragma unroll
    for (int o = 16; o > 0; o >>= 1) s += __shfl_xor_sync(0xffffffffu, s, o);
    __shared__ float red[8];
    const int lane = t & 31, wid = t >> 5;
    if (lane == 0) red[wid] = s;
    __syncthreads();
    if (wid == 0) {
        s = (lane < 8) ? red[lane] : 0.f;
#pragma unroll
        for (int o = 4; o > 0; o >>= 1) s += __shfl_xor_sync(0xffffffffu, s, o);
        if (lane == 0) red[0] = s;
    }
    __syncthreads();
    const float inv = rsqrtf(red[0] * (1.0f / (float)DMODEL) + 1e-6f) *
                      (mask ? mask[m] : 1.f);
    float wv[8];
    *(float4*)&wv[0] = *(const float4*)(w + t * 8);
    *(float4*)&wv[4] = *(const float4*)(w + t * 8 + 4);
#pragma unroll
    for (int j = 0; j < 8; j++) v[j] = v[j] * inv * wv[j];
    uint32_t hi[4], lo[4];
    cvt8u(v, hi, lo);
    const int st = t >> 2, c = t & 3, r = m & 127;
    uint8_t* base = dst + (size_t)((m >> 7) * 64 + st) * 16384 + swz(r, c);
    *(uint4*)base          = *(uint4*)hi;
    *(uint4*)(base + 8192) = *(uint4*)lo;
}

// ====== bf16x3 GEMM, swizzled packed operands, 3-stage K32 cp.async ======
#define OFF_AL 8192
#define OFF_BH 16384
#define OFF_BL 24576
#define STG    32768
#define GSMEM  (3*STG)

__global__ __launch_bounds__(256, 2) void gemm_mma(
    const uint8_t* __restrict__ Ap, const uint8_t* __restrict__ Bp,
    float* __restrict__ C, const float* __restrict__ addv,
    int N, int nslab, int addflag)
{
    extern __shared__ char sm[];
    const int tid  = threadIdx.x;
    const int warp = tid >> 5, lane = tid & 31;
    const int wm = warp >> 2, wn = warp & 3;
    const uint32_t sbase = smem_u32(sm);

    const uint8_t* aT = Ap + (size_t)blockIdx.x * nslab * 16384;
    const uint8_t* bT = Bp + (size_t)blockIdx.y * nslab * 16384;

    float acc[4][4][4];
#pragma unroll
    for (int i = 0; i < 4; i++)
#pragma unroll
        for (int j = 0; j < 4; j++)
#pragma unroll
            for (int r = 0; r < 4; r++) acc[i][j][r] = 0.f;

#pragma unroll
    for (int ss = 0; ss < 2; ss++) {
        const uint32_t d = sbase + (uint32_t)ss * STG;
        const size_t o = (size_t)ss * 16384;
#pragma unroll
        for (int j = 0; j < 4; j++) {
            const uint32_t cid = (uint32_t)tid * 16 + (uint32_t)j * 4096;
            CPASYNC16(d + cid,         aT + o + cid);
            CPASYNC16(d + 16384 + cid, bT + o + cid);
        }
        asm volatile("cp.async.commit_group;" ::: "memory");
    }

    const int lrow  = lane & 15;
    const int lcsel = lane >> 4;

    int cur = 0;
    for (int s = 0; s < nslab; s++) {
        if (s + 1 < nslab) { asm volatile("cp.async.wait_group 1;" ::: "memory"); }
        else               { asm volatile("cp.async.wait_group 0;" ::: "memory"); }
        __syncthreads();

        if (s + 2 < nslab) {
            int nx2 = cur + 2; if (nx2 >= 3) nx2 -= 3;
            const uint32_t d = sbase + (uint32_t)nx2 * STG;
            const size_t o = (size_t)(s + 2) * 16384;
#pragma unroll
            for (int j = 0; j < 4; j++) {
                const uint32_t cid = (uint32_t)tid * 16 + (uint32_t)j * 4096;
                CPASYNC16(d + cid,         aT + o + cid);
                CPASYNC16(d + 16384 + cid, bT + o + cid);
            }
            asm volatile("cp.async.commit_group;" ::: "memory");
        }

        const uint32_t stb = sbase + (uint32_t)cur * STG;
#pragma unroll
        for (int ks = 0; ks < 2; ks++) {
            const int kc = ks * 2 + lcsel;
            uint32_t bh[2][4], bl[2][4];
#pragma unroll
            for (int bt = 0; bt < 2; bt++) {
                const uint32_t off = swz(wn*32 + bt*16 + lrow, kc);
                LDSM_X4(bh[bt], stb + OFF_BH + off);
                LDSM_X4(bl[bt], stb + OFF_BL + off);
            }
#pragma unroll
            for (int mt = 0; mt < 4; mt++) {
                uint32_t ah[4], al[4];
                const uint32_t off = swz(wm*64 + mt*16 + lrow, kc);
                LDSM_X4(ah, stb + off);
                LDSM_X4(al, stb + OFF_AL + off);
#pragma unroll
                for (int nt = 0; nt < 4; nt++) {
                    const int bt = nt >> 1, sel = nt & 1;
                    const uint32_t b0h = bh[bt][sel], b1h = bh[bt][2+sel];
                    const uint32_t b0l = bl[bt][sel], b1l = bl[bt][2+sel];
                    MMA16816(acc[mt][nt], ah, b0h, b1h);
                    MMA16816(acc[mt][nt], al, b0h, b1h);
                    MMA16816(acc[mt][nt], ah, b0l, b1l);
                }
            }
        }
        if (++cur == 3) cur = 0;
    }

    const int g  = lane >> 2;
    const int t4 = lane & 3;
    const int bm = blockIdx.x * 128, bn = blockIdx.y * 128;
#pragma unroll
    for (int mt = 0; mt < 4; mt++) {
        const int row = bm + wm*64 + mt*16 + g;
#pragma unroll
        for (int nt = 0; nt < 4; nt++) {
            const int col = bn + wn*32 + nt*8 + t4*2;
            if (col < N) {
                float2 v0 = make_float2(acc[mt][nt][0], acc[mt][nt][1]);
                float2 v1 = make_float2(acc[mt][nt][2], acc[mt][nt][3]);
                const size_t i0 = (size_t)row * N + col;
                const size_t i1 = (size_t)(row + 8) * N + col;
                if (addflag) {
                    const float2 a0 = *(const float2*)(addv + i0);
                    const float2 a1 = *(const float2*)(addv + i1);
                    v0.x += a0.x; v0.y += a0.y; v1.x += a1.x; v1.y += a1.y;
                }
                *(float2*)(C + i0) = v0;
                *(float2*)(C + i1) = v1;
            }
        }
    }
}

// ---------------- causal depthwise conv1d (float4 over channels) ----------------
__global__ void conv_kernel(const float* __restrict__ zx,
                            const float* __restrict__ cw,
                            const float* __restrict__ cb,
                            float* __restrict__ xbc)
{
    const int m = blockIdx.x;
    const int t = m & (SEQ - 1);
#pragma unroll
    for (int it = 0; it < CONVDIM / 4 / 256; it++) {
        const int c = (it * 256 + threadIdx.x) * 4;
        float4 acc = *(const float4*)(cb + c);
        const float4 w0 = *(const float4*)(cw + (size_t)(c + 0) * 4);
        const float4 w1 = *(const float4*)(cw + (size_t)(c + 1) * 4);
        const float4 w2 = *(const float4*)(cw + (size_t)(c + 2) * 4);
        const float4 w3 = *(const float4*)(cw + (size_t)(c + 3) * 4);
#pragma unroll
        for (int j = 0; j < 4; j++) {
            const int tt = t - 3 + j;
            if (tt >= 0) {
                const float4 v = *(const float4*)(zx + (size_t)(m - 3 + j) * DPROJ + DINNER + c);
                const float wj0 = (&w0.x)[j], wj1 = (&w1.x)[j], wj2 = (&w2.x)[j], wj3 = (&w3.x)[j];
                acc.x = fmaf(wj0, v.x, acc.x);
                acc.y = fmaf(wj1, v.y, acc.y);
                acc.z = fmaf(wj2, v.z, acc.z);
                acc.w = fmaf(wj3, v.w, acc.w);
            }
        }
        *(float4*)(xbc + (size_t)m * CONVDIM + c) = acc;
    }
}

// ---------------- SSM scan, p-split x2: 2 blocks per (b,h), 32 p-rows each ----------------
// smem layout per buffer (floats): x[8][64] | B[8][64] | C[8][64] | z[8][64] | a[8]
#define CHK 8
#define SBUF 2064
__global__ __launch_bounds__(256) void scan_kernel(
    const float* __restrict__ xbc, const float* __restrict__ zx,
    const float* __restrict__ Dv, const float* __restrict__ zb,
    float* __restrict__ gated)
{
    const int blk = blockIdx.x;          // 0..127
    const int bh = blk >> 1;
    const int b = bh >> 5;
    const int h = bh & 31;
    const int half = blk & 1;
    const int tid = threadIdx.x;
    const int p = half * 32 + (tid >> 3);
    const int q = tid & 7;
    const int n0 = q << 3;

    __shared__ __align__(16) float sd[2][SBUF];

    int lts[9], loff[9], lkind[9], lsh[9];
    bool lvalid[9];
#pragma unroll
    for (int k = 0; k < 9; k++) {
        const int e = tid + k * 256;
        lvalid[k] = (e < CHK * 257);
        const int tsub = e / 257;
        const int j = e - tsub * 257;
        lts[k] = tsub;
        if (j < 64)        { lkind[k] = 0; loff[k] = h * HEADDIM + j;                     lsh[k] = tsub*64 + j; }
        else if (j < 128)  { lkind[k] = 0; loff[k] = DINNER + h * DSTATE + (j - 64);      lsh[k] = 512 + tsub*64 + (j-64); }
        else if (j < 192)  { lkind[k] = 0; loff[k] = DINNER + NHEADS*DSTATE + h*DSTATE + (j-128); lsh[k] = 1024 + tsub*64 + (j-128); }
        else if (j < 256)  { lkind[k] = 1; loff[k] = h * HEADDIM + (j - 192);             lsh[k] = 1536 + tsub*64 + (j-192); }
        else               { lkind[k] = 2; loff[k] = 2*DINNER + 2*NHEADS*DSTATE + h;      lsh[k] = 2048 + tsub; }
    }
#pragma unroll
    for (int k = 0; k < 9; k++) {
        if (lvalid[k]) {
            const size_t m = (size_t)b * SEQ + lts[k];
            float v;
            if (lkind[k] == 0) v = xbc[m * CONVDIM + loff[k]];
            else               v = zx[m * DPROJ + loff[k]];
            if (lkind[k] == 2) v = 1.f / (1.f + expf(v));
            sd[0][lsh[k]] = v;
        }
    }
    __syncthreads();

    float st[8];
#pragma unroll
    for (int i = 0; i < 8; i++) st[i] = 0.f;
    const float Dh = Dv[h];
    const float zbias = zb[h * HEADDIM + p];

    const int NC = SEQ / CHK;
    for (int c = 0; c < NC; c++) {
        const int cur = c & 1;
        const bool pre = (c + 1 < NC);
        float regv[9];
        if (pre) {
#pragma unroll
            for (int k = 0; k < 9; k++) {
                if (lvalid[k]) {
                    const size_t m = (size_t)b * SEQ + (c + 1) * CHK + lts[k];
                    float v;
                    if (lkind[k] == 0) v = xbc[m * CONVDIM + loff[k]];
                    else               v = zx[m * DPROJ + loff[k]];
                    if (lkind[k] == 2) v = 1.f / (1.f + expf(v));
                    regv[k] = v;
                }
            }
        }
        const float* sb = sd[cur];
#pragma unroll
        for (int tsub = 0; tsub < CHK; tsub++) {
            const float a  = sb[2048 + tsub];
            const float xv = sb[tsub*64 + p];
            const float4* Bp4 = (const float4*)(sb + 512 + tsub*64 + n0);
            const float4* Cp4 = (const float4*)(sb + 1024 + tsub*64 + n0);
            float Bv[8], Cv[8];
            *(float4*)&Bv[0] = Bp4[0]; *(float4*)&Bv[4] = Bp4[1];
            *(float4*)&Cv[0] = Cp4[0]; *(float4*)&Cv[4] = Cp4[1];
            float y = 0.f;
#pragma unroll
            for (int i = 0; i < 8; i++) {
                st[i] = a * st[i] + xv * Bv[i];
                y = fmaf(st[i], Cv[i], y);
            }
            y += __shfl_xor_sync(0xffffffffu, y, 1);
            y += __shfl_xor_sync(0xffffffffu, y, 2);
            y += __shfl_xor_sync(0xffffffffu, y, 4);
            if (q == 0) {
                const size_t m = (size_t)b * SEQ + c * CHK + tsub;
                const float zval = sb[1536 + tsub*64 + p] + zbias;
                const float sig = 1.f / (1.f + expf(-zval));
                gated[m * DMODEL + h * HEADDIM + p] = (y + Dh * xv) * (zval * sig);
            }
        }
        if (pre) {
#pragma unroll
            for (int k = 0; k < 9; k++)
                if (lvalid[k]) sd[cur ^ 1][lsh[k]] = regv[k];
        }
        __syncthreads();
    }
}

// ---------------- launcher ----------------
extern "C" void kernel_launch(void* const* d_in, const int* in_sizes, int n_in,
                              void* d_out, int out_size)
{
    (void)in_sizes; (void)n_in; (void)out_size;
    const float* hidden     = (const float*)d_in[0];
    const float* mask       = (const float*)d_in[1];
    const float* in_proj_w  = (const float*)d_in[2];
    const float* conv_w     = (const float*)d_in[3];
    const float* conv_b     = (const float*)d_in[4];
    const float* z_bias     = (const float*)d_in[5];
    const float* Dv         = (const float*)d_in[6];
    const float* out_proj_w = (const float*)d_in[7];
    const float* ln1_w      = (const float*)d_in[8];
    const float* ln2_w      = (const float*)d_in[9];
    const float* gate_w     = (const float*)d_in[10];
    const float* up_w       = (const float*)d_in[11];
    const float* down_w     = (const float*)d_in[12];
    float* out = (float*)d_out;

    float *zx, *xbc, *gated, *res2, *guf;
    uint8_t *pa, *pb;
    cudaGetSymbolAddress((void**)&zx,    g_zx);
    cudaGetSymbolAddress((void**)&xbc,   g_xbc);
    cudaGetSymbolAddress((void**)&gated, g_gated);
    cudaGetSymbolAddress((void**)&res2,  g_res2);
    cudaGetSymbolAddress((void**)&guf,   g_guf);
    cudaGetSymbolAddress((void**)&pa,    g_pa);
    cudaGetSymbolAddress((void**)&pb,    g_pb);

    uint8_t* pbI = pb + (size_t)PB_I * 16384;
    uint8_t* pbO = pb + (size_t)PB_O * 16384;
    uint8_t* pbG = pb + (size_t)PB_G * 16384;
    uint8_t* pbD = pb + (size_t)PB_D * 16384;

    cudaFuncSetAttribute(gemm_mma, cudaFuncAttributeMaxDynamicSharedMemorySize, GSMEM);
    const int PKG = 4096;

    cudaStream_t s2;
    cudaStreamCreateWithFlags(&s2, cudaStreamNonBlocking);
    cudaEvent_t evF, evI, evO, evGU, evD;
    cudaEventCreateWithFlags(&evF,  cudaEventDisableTiming);
    cudaEventCreateWithFlags(&evI,  cudaEventDisableTiming);
    cudaEventCreateWithFlags(&evO,  cudaEventDisableTiming);
    cudaEventCreateWithFlags(&evGU, cudaEventDisableTiming);
    cudaEventCreateWithFlags(&evD,  cudaEventDisableTiming);

    cudaEventRecord(evF, 0);
    cudaStreamWaitEvent(s2, evF, 0);
    pack_tiles<<<PKG, 256, 0, s2>>>(in_proj_w, pbI, 2048, 64, DPROJ, 65*64*512);
    cudaEventRecord(evI, s2);
    pack_tiles<<<PKG, 256, 0, s2>>>(out_proj_w, pbO, 2048, 64, DMODEL, 16*64*512);
    cudaEventRecord(evO, s2);
    pack_tiles<<<PKG, 256, 0, s2>>>(gate_w, pbG, 2048, 64, INTERSZ, 43*64*512);
    pack_tiles<<<PKG, 256, 0, s2>>>(up_w, pbG + (size_t)43*64*16384, 2048, 64, INTERSZ, 43*64*512);
    cudaEventRecord(evGU, s2);
    pack_tiles<<<PKG, 256, 0, s2>>>(down_w, pbD, 5504, 172, DMODEL, 16*172*512);
    cudaEventRecord(evD, s2);

    // ---- main chain ----
    rmsnorm_pack<<<MROWS, 256>>>(hidden, ln1_w, mask, pa);
    cudaStreamWaitEvent(0, evI, 0);
    gemm_mma<<<dim3(32, 65), 256, GSMEM>>>(pa, pbI, zx, nullptr, DPROJ, 64, 0);

    conv_kernel<<<MROWS, 256>>>(zx, conv_w, conv_b, xbc);
    scan_kernel<<<2 * BATCH * NHEADS, 256>>>(xbc, zx, Dv, z_bias, gated);

    pack_tiles<<<PKG, 256>>>(gated, pa, 2048, 64, MROWS, 32*64*512);
    cudaStreamWaitEvent(0, evO, 0);
    gemm_mma<<<dim3(32, 16), 256, GSMEM>>>(pa, pbO, res2, hidden, DMODEL, 64, 1);

    // ---- MLP ----
    rmsnorm_pack<<<MROWS, 256>>>(res2, ln2_w, nullptr, pa);
    cudaStreamWaitEvent(0, evGU, 0);
    gemm_mma<<<dim3(32, 86), 256, GSMEM>>>(pa, pbG, guf, nullptr, 11008, 64, 0);

    pack_silu<<<PKG, 256>>>(guf, pa, 32*172*512);
    cudaStreamWaitEvent(0, evD, 0);
    gemm_mma<<<dim3(32, 16), 256, GSMEM>>>(pa, pbD, out, res2, DMODEL, 172, 1);
}

// round 14
// speedup vs baseline: 1.1063x; 1.0163x over previous
#include <cuda_runtime.h>
#include <cuda_bf16.h>
#include <math.h>
#include <stdint.h>

#define BATCH   2
#define SEQ     2048
#define DMODEL  2048
#define NHEADS  32
#define DSTATE  64
#define HEADDIM 64
#define DCONV   4
#define INTERSZ 5504
#define DINNER  DMODEL
#define CONVDIM (DINNER + 2*NHEADS*DSTATE)              /* 6144 */
#define DPROJ   (2*DINNER + 2*NHEADS*DSTATE + NHEADS)   /* 8224 */
#define MROWS   (BATCH*SEQ)                             /* 4096 */

// ---------------- scratch ----------------
__device__ float g_zx   [(size_t)MROWS * DPROJ];
__device__ float g_xbc  [(size_t)MROWS * CONVDIM];
__device__ float g_gated[(size_t)MROWS * DMODEL];
__device__ float g_res2 [(size_t)MROWS * DMODEL];
#define PB_I 0
#define PB_O (65*64)
#define PB_GU (PB_O + 16*64)
#define PB_D (PB_GU + 86*64)
#define PB_TILES (PB_D + 16*172)
__device__ __align__(128) uint8_t g_pa [(size_t)32 * 64  * 16384];
__device__ __align__(128) uint8_t g_pa2[(size_t)32 * 172 * 16384];    /* 90 MB  */
__device__ __align__(128) uint8_t g_pb [(size_t)PB_TILES * 16384];    /* 220 MB */

static __device__ __forceinline__ uint32_t smem_u32(const void* p) {
    uint32_t a;
    asm("{ .reg .u64 t; cvta.to.shared.u64 t, %1; cvt.u32.u64 %0, t; }" : "=r"(a) : "l"(p));
    return a;
}

#define LDSM_X4(r, addr) \
    asm volatile("ldmatrix.sync.aligned.m8n8.x4.shared.b16 {%0,%1,%2,%3}, [%4];" \
        : "=r"((r)[0]), "=r"((r)[1]), "=r"((r)[2]), "=r"((r)[3]) : "r"(addr))

#define MMA16816(c, a, b0, b1) \
    asm volatile("mma.sync.aligned.m16n8k16.row.col.f32.bf16.bf16.f32 " \
        "{%0,%1,%2,%3}, {%4,%5,%6,%7}, {%8,%9}, {%0,%1,%2,%3};" \
        : "+f"((c)[0]), "+f"((c)[1]), "+f"((c)[2]), "+f"((c)[3]) \
        : "r"((a)[0]), "r"((a)[1]), "r"((a)[2]), "r"((a)[3]), "r"(b0), "r"(b1))

#define CPASYNC16(dst, src) \
    asm volatile("cp.async.cg.shared.global [%0], [%1], 16;" :: "r"(dst), "l"(src))

static __device__ __forceinline__ void cvt8u(const float* v, uint32_t* hi, uint32_t* lo) {
#pragma unroll
    for (int j = 0; j < 4; j++) {
        __nv_bfloat162 h = __float22bfloat162_rn(make_float2(v[2*j], v[2*j+1]));
        float g0 = __bfloat162float(h.x), g1 = __bfloat162float(h.y);
        __nv_bfloat162 l = __float22bfloat162_rn(make_float2(v[2*j]-g0, v[2*j+1]-g1));
        hi[j] = *(uint32_t*)&h; lo[j] = *(uint32_t*)&l;
    }
}

static __device__ __forceinline__ uint32_t swz(int r, int c) {
    return (uint32_t)(r * 64 + ((c ^ ((r >> 1) & 3)) << 4));
}

// ---------------- pack: fp32 -> bf16 hi/lo swizzled 128x32 tiles ----------------
__global__ void pack_tiles(const float* __restrict__ src, uint8_t* __restrict__ dst,
                           int K, int nslab, int Nreal, int nChunks)
{
    for (int id = blockIdx.x * blockDim.x + threadIdx.x; id < nChunks;
         id += gridDim.x * blockDim.x) {
        const int tile = id >> 9;
        const int w = id & 511;
        const int r = w >> 2, c = w & 3;
        const int mt = tile / nslab;
        const int s  = tile - mt * nslab;
        const int row = mt * 128 + r;
        float v[8] = {0.f,0.f,0.f,0.f,0.f,0.f,0.f,0.f};
        if (row < Nreal) {
            const float* p = src + (size_t)row * K + s * 32 + c * 8;
            *(float4*)&v[0] = *(const float4*)p;
            *(float4*)&v[4] = *(const float4*)(p + 4);
        }
        uint32_t hi[4], lo[4];
        cvt8u(v, hi, lo);
        uint8_t* base = dst + (size_t)tile * 16384 + swz(r, c);
        *(uint4*)base           = *(uint4*)hi;
        *(uint4*)(base + 8192)  = *(uint4*)lo;
    }
}

// ---------------- pack gate/up interleaved B tiles (8-col groups alternate) ----------------
__global__ void pack_gu(const float* __restrict__ gate_w, const float* __restrict__ up_w,
                        uint8_t* __restrict__ dst, int nChunks)
{
    for (int id = blockIdx.x * blockDim.x + threadIdx.x; id < nChunks;
         id += gridDim.x * blockDim.x) {
        const int tile = id >> 9;
        const int w = id & 511;
        const int r = w >> 2, c = w & 3;
        const int jt = tile >> 6;
        const int s  = tile & 63;
        const int g = r >> 3, i = r & 7;
        const int lcol = jt * 64 + (g >> 1) * 8 + i;     // logical row in weight (<5504)
        const float* src = (g & 1) ? up_w : gate_w;
        const float* p = src + (size_t)lcol * 2048 + s * 32 + c * 8;
        float v[8];
        *(float4*)&v[0] = *(const float4*)p;
        *(float4*)&v[4] = *(const float4*)(p + 4);
        uint32_t hi[4], lo[4];
        cvt8u(v, hi, lo);
        uint8_t* base = dst + (size_t)tile * 16384 + swz(r, c);
        *(uint4*)base           = *(uint4*)hi;
        *(uint4*)(base + 8192)  = *(uint4*)lo;
    }
}

// ---------------- fused RMSNorm (optionally * mask) -> packed A tiles ----------------
__global__ __launch_bounds__(256) void rmsnorm_pack(const float* __restrict__ x,
                                                    const float* __restrict__ w,
                                                    const float* __restrict__ mask,
                                                    uint8_t* __restrict__ dst)
{
    const int m = blockIdx.x;
    const int t = threadIdx.x;
    const float* row = x + (size_t)m * DMODEL;
    float v[8];
    *(float4*)&v[0] = *(const float4*)(row + t * 8);
    *(float4*)&v[4] = *(const float4*)(row + t * 8 + 4);
    float s = 0.f;
#pragma unroll
    for (int j = 0; j < 8; j++) s += v[j] * v[j];
#pragma unroll
    for (int o = 16; o > 0; o >>= 1) s += __shfl_xor_sync(0xffffffffu, s, o);
    __shared__ float red[8];
    const int lane = t & 31, wid = t >> 5;
    if (lane == 0) red[wid] = s;
    __syncthreads();
    if (wid == 0) {
        s = (lane < 8) ? red[lane] : 0.f;
#pragma unroll
        for (int o = 4; o > 0; o >>= 1) s += __shfl_xor_sync(0xffffffffu, s, o);
        if (lane == 0) red[0] = s;
    }
    __syncthreads();
    const float inv = rsqrtf(red[0] * (1.0f / (float)DMODEL) + 1e-6f) *
                      (mask ? mask[m] : 1.f);
    float wv[8];
    *(float4*)&wv[0] = *(const float4*)(w + t * 8);
    *(float4*)&wv[4] = *(const float4*)(w + t * 8 + 4);
#pragma unroll
    for (int j = 0; j < 8; j++) v[j] = v[j] * inv * wv[j];
    uint32_t hi[4], lo[4];
    cvt8u(v, hi, lo);
    const int st = t >> 2, c = t & 3, r = m & 127;
    uint8_t* base = dst + (size_t)((m >> 7) * 64 + st) * 16384 + swz(r, c);
    *(uint4*)base          = *(uint4*)hi;
    *(uint4*)(base + 8192) = *(uint4*)lo;
}

// ====== shared GEMM mainloop (3-stage K32 cp.async, bf16x3) ======
#define OFF_AL 8192
#define OFF_BH 16384
#define OFF_BL 24576
#define STG    32768
#define GSMEM  (3*STG)

#define GEMM_MAINLOOP()                                                            \
    extern __shared__ char sm[];                                                   \
    const int tid  = threadIdx.x;                                                  \
    const int warp = tid >> 5, lane = tid & 31;                                    \
    const int wm = warp >> 2, wn = warp & 3;                                       \
    const uint32_t sbase = smem_u32(sm);                                           \
    const uint8_t* aT = Ap + (size_t)blockIdx.x * nslab * 16384;                   \
    const uint8_t* bT = Bp + (size_t)blockIdx.y * nslab * 16384;                   \
    float acc[4][4][4];                                                            \
    _Pragma("unroll") for (int i = 0; i < 4; i++)                                  \
    _Pragma("unroll") for (int j = 0; j < 4; j++)                                  \
    _Pragma("unroll") for (int r = 0; r < 4; r++) acc[i][j][r] = 0.f;              \
    _Pragma("unroll")                                                              \
    for (int ss = 0; ss < 2; ss++) {                                               \
        const uint32_t d = sbase + (uint32_t)ss * STG;                             \
        const size_t o = (size_t)ss * 16384;                                       \
        _Pragma("unroll")                                                          \
        for (int j = 0; j < 4; j++) {                                              \
            const uint32_t cid = (uint32_t)tid * 16 + (uint32_t)j * 4096;          \
            CPASYNC16(d + cid,         aT + o + cid);                              \
            CPASYNC16(d + 16384 + cid, bT + o + cid);                              \
        }                                                                          \
        asm volatile("cp.async.commit_group;" ::: "memory");                      \
    }                                                                              \
    const int lrow  = lane & 15;                                                   \
    const int lcsel = lane >> 4;                                                   \
    int cur = 0;                                                                   \
    for (int s = 0; s < nslab; s++) {                                              \
        if (s + 1 < nslab) { asm volatile("cp.async.wait_group 1;" ::: "memory"); }\
        else               { asm volatile("cp.async.wait_group 0;" ::: "memory"); }\
        __syncthreads();                                                           \
        if (s + 2 < nslab) {                                                       \
            int nx2 = cur + 2; if (nx2 >= 3) nx2 -= 3;                             \
            const uint32_t d = sbase + (uint32_t)nx2 * STG;                        \
            const size_t o = (size_t)(s + 2) * 16384;                              \
            _Pragma("unroll")                                                      \
            for (int j = 0; j < 4; j++) {                                          \
                const uint32_t cid = (uint32_t)tid * 16 + (uint32_t)j * 4096;      \
                CPASYNC16(d + cid,         aT + o + cid);                          \
                CPASYNC16(d + 16384 + cid, bT + o + cid);                          \
            }                                                                      \
            asm volatile("cp.async.commit_group;" ::: "memory");                  \
        }                                                                          \
        const uint32_t stb = sbase + (uint32_t)cur * STG;                          \
        _Pragma("unroll")                                                          \
        for (int ks = 0; ks < 2; ks++) {                                           \
            const int kc = ks * 2 + lcsel;                                         \
            uint32_t bh[2][4], bl[2][4];                                           \
            _Pragma("unroll")                                                      \
            for (int bt = 0; bt < 2; bt++) {                                       \
                const uint32_t off = swz(wn*32 + bt*16 + lrow, kc);                \
                LDSM_X4(bh[bt], stb + OFF_BH + off);                               \
                LDSM_X4(bl[bt], stb + OFF_BL + off);                               \
            }                                                                      \
            _Pragma("unroll")                                                      \
            for (int mt = 0; mt < 4; mt++) {                                       \
                uint32_t ah[4], al[4];                                             \
                const uint32_t off = swz(wm*64 + mt*16 + lrow, kc);                \
                LDSM_X4(ah, stb + off);                                            \
                LDSM_X4(al, stb + OFF_AL + off);                                   \
                _Pragma("unroll")                                                  \
                for (int nt = 0; nt < 4; nt++) {                                   \
                    const int bt = nt >> 1, sel = nt & 1;                          \
                    const uint32_t b0h = bh[bt][sel], b1h = bh[bt][2+sel];         \
                    const uint32_t b0l = bl[bt][sel], b1l = bl[bt][2+sel];         \
                    MMA16816(acc[mt][nt], ah, b0h, b1h);                           \
                    MMA16816(acc[mt][nt], al, b0h, b1h);                           \
                    MMA16816(acc[mt][nt], ah, b0l, b1l);                           \
                }                                                                  \
            }                                                                      \
        }                                                                          \
        if (++cur == 3) cur = 0;                                                   \
    }

__global__ __launch_bounds__(256, 2) void gemm_mma(
    const uint8_t* __restrict__ Ap, const uint8_t* __restrict__ Bp,
    float* __restrict__ C, const float* __restrict__ addv,
    int N, int nslab, int addflag)
{
    GEMM_MAINLOOP()
    const int g  = lane >> 2;
    const int t4 = lane & 3;
    const int bm = blockIdx.x * 128, bn = blockIdx.y * 128;
#pragma unroll
    for (int mt = 0; mt < 4; mt++) {
        const int row = bm + wm*64 + mt*16 + g;
#pragma unroll
        for (int nt = 0; nt < 4; nt++) {
            const int col = bn + wn*32 + nt*8 + t4*2;
            if (col < N) {
                float2 v0 = make_float2(acc[mt][nt][0], acc[mt][nt][1]);
                float2 v1 = make_float2(acc[mt][nt][2], acc[mt][nt][3]);
                const size_t i0 = (size_t)row * N + col;
                const size_t i1 = (size_t)(row + 8) * N + col;
                if (addflag) {
                    const float2 a0 = *(const float2*)(addv + i0);
                    const float2 a1 = *(const float2*)(addv + i1);
                    v0.x += a0.x; v0.y += a0.y; v1.x += a1.x; v1.y += a1.y;
                }
                *(float2*)(C + i0) = v0;
                *(float2*)(C + i1) = v1;
            }
        }
    }
}

// gate/up GEMM with fused silu(g)*u epilogue writing packed bf16 hi/lo A tiles
__global__ __launch_bounds__(256, 2) void gemm_mma_silu(
    const uint8_t* __restrict__ Ap, const uint8_t* __restrict__ Bp,
    uint8_t* __restrict__ paOut, int nslab)
{
    GEMM_MAINLOOP()
    const int g  = lane >> 2;
    const int t4 = lane & 3;
    const int bm = blockIdx.x * 128;
#pragma unroll
    for (int mt = 0; mt < 4; mt++) {
        const int r0 = bm + wm*64 + mt*16 + g;
#pragma unroll
        for (int ntp = 0; ntp < 2; ntp++) {
            const float* ga = acc[mt][2*ntp];
            const float* ua = acc[mt][2*ntp + 1];
            const int L = blockIdx.y * 64 + (wn*2 + ntp) * 8 + t4 * 2;
            const int c16 = (L >> 3) & 3;
            const int ib = (L & 7) * 2;
#pragma unroll
            for (int rr = 0; rr < 2; rr++) {
                const int row = r0 + rr * 8;
                const float g0 = ga[2*rr], g1 = ga[2*rr + 1];
                const float v0 = ua[2*rr]     * g0 / (1.f + expf(-g0));
                const float v1 = ua[2*rr + 1] * g1 / (1.f + expf(-g1));
                __nv_bfloat162 h = __float22bfloat162_rn(make_float2(v0, v1));
                const float h0 = __bfloat162float(h.x), h1 = __bfloat162float(h.y);
                __nv_bfloat162 l = __float22bfloat162_rn(make_float2(v0 - h0, v1 - h1));
                uint8_t* base = paOut + ((size_t)(row >> 7) * 172 + (L >> 5)) * 16384
                                + swz(row & 127, c16) + ib;
                *(uint32_t*)base          = *(uint32_t*)&h;
                *(uint32_t*)(base + 8192) = *(uint32_t*)&l;
            }
        }
    }
}

// ---------------- causal depthwise conv1d (float4 over channels) ----------------
__global__ void conv_kernel(const float* __restrict__ zx,
                            const float* __restrict__ cw,
                            const float* __restrict__ cb,
                            float* __restrict__ xbc)
{
    const int m = blockIdx.x;
    const int t = m & (SEQ - 1);
#pragma unroll
    for (int it = 0; it < CONVDIM / 4 / 256; it++) {
        const int c = (it * 256 + threadIdx.x) * 4;
        float4 acc = *(const float4*)(cb + c);
        const float4 w0 = *(const float4*)(cw + (size_t)(c + 0) * 4);
        const float4 w1 = *(const float4*)(cw + (size_t)(c + 1) * 4);
        const float4 w2 = *(const float4*)(cw + (size_t)(c + 2) * 4);
        const float4 w3 = *(const float4*)(cw + (size_t)(c + 3) * 4);
#pragma unroll
        for (int j = 0; j < 4; j++) {
            const int tt = t - 3 + j;
            if (tt >= 0) {
                const float4 v = *(const float4*)(zx + (size_t)(m - 3 + j) * DPROJ + DINNER + c);
                acc.x = fmaf((&w0.x)[j], v.x, acc.x);
                acc.y = fmaf((&w1.x)[j], v.y, acc.y);
                acc.z = fmaf((&w2.x)[j], v.z, acc.z);
                acc.w = fmaf((&w3.x)[j], v.w, acc.w);
            }
        }
        *(float4*)(xbc + (size_t)m * CONVDIM + c) = acc;
    }
}

// ---------------- SSM scan, p-split x4: 4 blocks per (b,h), 16 p-rows each ----------------
#define CHK 8
#define SBUF 2064
__global__ __launch_bounds__(256) void scan_kernel(
    const float* __restrict__ xbc, const float* __restrict__ zx,
    const float* __restrict__ Dv, const float* __restrict__ zb,
    float* __restrict__ gated)
{
    const int blk = blockIdx.x;          // 0..255
    const int bh = blk >> 2;
    const int b = bh >> 5;
    const int h = bh & 31;
    const int quarter = blk & 3;
    const int tid = threadIdx.x;
    const int p = quarter * 16 + (tid >> 4);
    const int q = tid & 15;
    const int n0 = q << 2;

    __shared__ __align__(16) float sd[2][SBUF];

    int lts[9], loff[9], lkind[9], lsh[9];
    bool lvalid[9];
#pragma unroll
    for (int k = 0; k < 9; k++) {
        const int e = tid + k * 256;
        lvalid[k] = (e < CHK * 257);
        const int tsub = e / 257;
        const int j = e - tsub * 257;
        lts[k] = tsub;
        if (j < 64)        { lkind[k] = 0; loff[k] = h * HEADDIM + j;                     lsh[k] = tsub*64 + j; }
        else if (j < 128)  { lkind[k] = 0; loff[k] = DINNER + h * DSTATE + (j - 64);      lsh[k] = 512 + tsub*64 + (j-64); }
        else if (j < 192)  { lkind[k] = 0; loff[k] = DINNER + NHEADS*DSTATE + h*DSTATE + (j-128); lsh[k] = 1024 + tsub*64 + (j-128); }
        else if (j < 256)  { lkind[k] = 1; loff[k] = h * HEADDIM + (j - 192);             lsh[k] = 1536 + tsub*64 + (j-192); }
        else               { lkind[k] = 2; loff[k] = 2*DINNER + 2*NHEADS*DSTATE + h;      lsh[k] = 2048 + tsub; }
    }
#pragma unroll
    for (int k = 0; k < 9; k++) {
        if (lvalid[k]) {
            const size_t m = (size_t)b * SEQ + lts[k];
            float v;
            if (lkind[k] == 0) v = xbc[m * CONVDIM + loff[k]];
            else               v = zx[m * DPROJ + loff[k]];
            if (lkind[k] == 2) v = 1.f / (1.f + expf(v));
            sd[0][lsh[k]] = v;
        }
    }
    __syncthreads();

    float st[4];
#pragma unroll
    for (int i = 0; i < 4; i++) st[i] = 0.f;
    const float Dh = Dv[h];
    const float zbias = zb[h * HEADDIM + p];

    const int NC = SEQ / CHK;
    for (int c = 0; c < NC; c++) {
        const int cur = c & 1;
        const bool pre = (c + 1 < NC);
        float regv[9];
        if (pre) {
#pragma unroll
            for (int k = 0; k < 9; k++) {
                if (lvalid[k]) {
                    const size_t m = (size_t)b * SEQ + (c + 1) * CHK + lts[k];
                    float v;
                    if (lkind[k] == 0) v = xbc[m * CONVDIM + loff[k]];
                    else               v = zx[m * DPROJ + loff[k]];
                    if (lkind[k] == 2) v = 1.f / (1.f + expf(v));
                    regv[k] = v;
                }
            }
        }
        const float* sb = sd[cur];
#pragma unroll
        for (int tsub = 0; tsub < CHK; tsub++) {
            const float a  = sb[2048 + tsub];
            const float xv = sb[tsub*64 + p];
            float Bv[4], Cv[4];
            *(float4*)&Bv[0] = *(const float4*)(sb + 512 + tsub*64 + n0);
            *(float4*)&Cv[0] = *(const float4*)(sb + 1024 + tsub*64 + n0);
            float y = 0.f;
#pragma unroll
            for (int i = 0; i < 4; i++) {
                st[i] = a * st[i] + xv * Bv[i];
                y = fmaf(st[i], Cv[i], y);
            }
            y += __shfl_xor_sync(0xffffffffu, y, 1);
            y += __shfl_xor_sync(0xffffffffu, y, 2);
            y += __shfl_xor_sync(0xffffffffu, y, 4);
            y += __shfl_xor_sync(0xffffffffu, y, 8);
            if (q == 0) {
                const size_t m = (size_t)b * SEQ + c * CHK + tsub;
                const float zval = sb[1536 + tsub*64 + p] + zbias;
                const float sig = 1.f / (1.f + expf(-zval));
                gated[m * DMODEL + h * HEADDIM + p] = (y + Dh * xv) * (zval * sig);
            }
        }
        if (pre) {
#pragma unroll
            for (int k = 0; k < 9; k++)
                if (lvalid[k]) sd[cur ^ 1][lsh[k]] = regv[k];
        }
        __syncthreads();
    }
}

// ---------------- launcher ----------------
extern "C" void kernel_launch(void* const* d_in, const int* in_sizes, int n_in,
                              void* d_out, int out_size)
{
    (void)in_sizes; (void)n_in; (void)out_size;
    const float* hidden     = (const float*)d_in[0];
    const float* mask       = (const float*)d_in[1];
    const float* in_proj_w  = (const float*)d_in[2];
    const float* conv_w     = (const float*)d_in[3];
    const float* conv_b     = (const float*)d_in[4];
    const float* z_bias     = (const float*)d_in[5];
    const float* Dv         = (const float*)d_in[6];
    const float* out_proj_w = (const float*)d_in[7];
    const float* ln1_w      = (const float*)d_in[8];
    const float* ln2_w      = (const float*)d_in[9];
    const float* gate_w     = (const float*)d_in[10];
    const float* up_w       = (const float*)d_in[11];
    const float* down_w     = (const float*)d_in[12];
    float* out = (float*)d_out;

    float *zx, *xbc, *gated, *res2;
    uint8_t *pa, *pa2, *pb;
    cudaGetSymbolAddress((void**)&zx,    g_zx);
    cudaGetSymbolAddress((void**)&xbc,   g_xbc);
    cudaGetSymbolAddress((void**)&gated, g_gated);
    cudaGetSymbolAddress((void**)&res2,  g_res2);
    cudaGetSymbolAddress((void**)&pa,    g_pa);
    cudaGetSymbolAddress((void**)&pa2,   g_pa2);
    cudaGetSymbolAddress((void**)&pb,    g_pb);

    uint8_t* pbI  = pb + (size_t)PB_I * 16384;
    uint8_t* pbO  = pb + (size_t)PB_O * 16384;
    uint8_t* pbGU = pb + (size_t)PB_GU * 16384;
    uint8_t* pbD  = pb + (size_t)PB_D * 16384;

    cudaFuncSetAttribute(gemm_mma, cudaFuncAttributeMaxDynamicSharedMemorySize, GSMEM);
    cudaFuncSetAttribute(gemm_mma_silu, cudaFuncAttributeMaxDynamicSharedMemorySize, GSMEM);
    const int PKG = 4096;

    cudaStream_t s2;
    cudaStreamCreateWithFlags(&s2, cudaStreamNonBlocking);
    cudaEvent_t evF, evI, evO, evGU, evD;
    cudaEventCreateWithFlags(&evF,  cudaEventDisableTiming);
    cudaEventCreateWithFlags(&evI,  cudaEventDisableTiming);
    cudaEventCreateWithFlags(&evO,  cudaEventDisableTiming);
    cudaEventCreateWithFlags(&evGU, cudaEventDisableTiming);
    cudaEventCreateWithFlags(&evD,  cudaEventDisableTiming);

    cudaEventRecord(evF, 0);
    cudaStreamWaitEvent(s2, evF, 0);
    pack_tiles<<<PKG, 256, 0, s2>>>(in_proj_w, pbI, 2048, 64, DPROJ, 65*64*512);
    cudaEventRecord(evI, s2);
    pack_tiles<<<PKG, 256, 0, s2>>>(out_proj_w, pbO, 2048, 64, DMODEL, 16*64*512);
    cudaEventRecord(evO, s2);
    pack_gu<<<PKG, 256, 0, s2>>>(gate_w, up_w, pbGU, 86*64*512);
    cudaEventRecord(evGU, s2);
    pack_tiles<<<PKG, 256, 0, s2>>>(down_w, pbD, 5504, 172, DMODEL, 16*172*512);
    cudaEventRecord(evD, s2);

    // ---- main chain ----
    rmsnorm_pack<<<MROWS, 256>>>(hidden, ln1_w, mask, pa);
    cudaStreamWaitEvent(0, evI, 0);
    gemm_mma<<<dim3(32, 65), 256, GSMEM>>>(pa, pbI, zx, nullptr, DPROJ, 64, 0);

    conv_kernel<<<MROWS, 256>>>(zx, conv_w, conv_b, xbc);
    scan_kernel<<<4 * BATCH * NHEADS, 256>>>(xbc, zx, Dv, z_bias, gated);

    pack_tiles<<<PKG, 256>>>(gated, pa, 2048, 64, MROWS, 32*64*512);
    cudaStreamWaitEvent(0, evO, 0);
    gemm_mma<<<dim3(32, 16), 256, GSMEM>>>(pa, pbO, res2, hidden, DMODEL, 64, 1);

    // ---- MLP ----
    rmsnorm_pack<<<MROWS, 256>>>(res2, ln2_w, nullptr, pa);
    cudaStreamWaitEvent(0, evGU, 0);
    gemm_mma_silu<<<dim3(32, 86), 256, GSMEM>>>(pa, pbGU, pa2, 64);

    cudaStreamWaitEvent(0, evD, 0);
    gemm_mma<<<dim3(32, 16), 256, GSMEM>>>(pa2, pbD, out, res2, DMODEL, 172, 1);
}

// round 15
// speedup vs baseline: 1.1082x; 1.0018x over previous
#include <cuda_runtime.h>
#include <cuda_bf16.h>
#include <math.h>
#include <stdint.h>

#define BATCH   2
#define SEQ     2048
#define DMODEL  2048
#define NHEADS  32
#define DSTATE  64
#define HEADDIM 64
#define DCONV   4
#define INTERSZ 5504
#define DINNER  DMODEL
#define CONVDIM (DINNER + 2*NHEADS*DSTATE)              /* 6144 */
#define DPROJ   (2*DINNER + 2*NHEADS*DSTATE + NHEADS)   /* 8224 */
#define MROWS   (BATCH*SEQ)                             /* 4096 */

// ---------------- scratch ----------------
__device__ float g_zx   [(size_t)MROWS * DPROJ];
__device__ float g_xbc  [(size_t)MROWS * CONVDIM];
__device__ float g_gated[(size_t)MROWS * DMODEL];
__device__ float g_res2 [(size_t)MROWS * DMODEL];
#define PB_I 0
#define PB_O (65*64)
#define PB_GU (PB_O + 16*64)
#define PB_D (PB_GU + 86*64)
#define PB_TILES (PB_D + 16*172)
__device__ __align__(128) uint8_t g_pa [(size_t)32 * 64  * 16384];
__device__ __align__(128) uint8_t g_pa2[(size_t)32 * 172 * 16384];    /* 90 MB  */
__device__ __align__(128) uint8_t g_pb [(size_t)PB_TILES * 16384];    /* 220 MB */

static __device__ __forceinline__ uint32_t smem_u32(const void* p) {
    uint32_t a;
    asm("{ .reg .u64 t; cvta.to.shared.u64 t, %1; cvt.u32.u64 %0, t; }" : "=r"(a) : "l"(p));
    return a;
}

#define LDSM_X4(r, addr) \
    asm volatile("ldmatrix.sync.aligned.m8n8.x4.shared.b16 {%0,%1,%2,%3}, [%4];" \
        : "=r"((r)[0]), "=r"((r)[1]), "=r"((r)[2]), "=r"((r)[3]) : "r"(addr))

#define MMA16816(c, a, b0, b1) \
    asm volatile("mma.sync.aligned.m16n8k16.row.col.f32.bf16.bf16.f32 " \
        "{%0,%1,%2,%3}, {%4,%5,%6,%7}, {%8,%9}, {%0,%1,%2,%3};" \
        : "+f"((c)[0]), "+f"((c)[1]), "+f"((c)[2]), "+f"((c)[3]) \
        : "r"((a)[0]), "r"((a)[1]), "r"((a)[2]), "r"((a)[3]), "r"(b0), "r"(b1))

#define CPASYNC16(dst, src) \
    asm volatile("cp.async.cg.shared.global [%0], [%1], 16;" :: "r"(dst), "l"(src))

static __device__ __forceinline__ void cvt8u(const float* v, uint32_t* hi, uint32_t* lo) {
#pragma unroll
    for (int j = 0; j < 4; j++) {
        __nv_bfloat162 h = __float22bfloat162_rn(make_float2(v[2*j], v[2*j+1]));
        float g0 = __bfloat162float(h.x), g1 = __bfloat162float(h.y);
        __nv_bfloat162 l = __float22bfloat162_rn(make_float2(v[2*j]-g0, v[2*j+1]-g1));
        hi[j] = *(uint32_t*)&h; lo[j] = *(uint32_t*)&l;
    }
}

static __device__ __forceinline__ uint32_t swz(int r, int c) {
    return (uint32_t)(r * 64 + ((c ^ ((r >> 1) & 3)) << 4));
}

// ---------------- pack: fp32 -> bf16 hi/lo swizzled 128x32 tiles ----------------
__global__ void pack_tiles(const float* __restrict__ src, uint8_t* __restrict__ dst,
                           int K, int nslab, int Nreal, int nChunks)
{
    for (int id = blockIdx.x * blockDim.x + threadIdx.x; id < nChunks;
         id += gridDim.x * blockDim.x) {
        const int tile = id >> 9;
        const int w = id & 511;
        const int r = w >> 2, c = w & 3;
        const int mt = tile / nslab;
        const int s  = tile - mt * nslab;
        const int row = mt * 128 + r;
        float v[8] = {0.f,0.f,0.f,0.f,0.f,0.f,0.f,0.f};
        if (row < Nreal) {
            const float* p = src + (size_t)row * K + s * 32 + c * 8;
            *(float4*)&v[0] = *(const float4*)p;
            *(float4*)&v[4] = *(const float4*)(p + 4);
        }
        uint32_t hi[4], lo[4];
        cvt8u(v, hi, lo);
        uint8_t* base = dst + (size_t)tile * 16384 + swz(r, c);
        *(uint4*)base           = *(uint4*)hi;
        *(uint4*)(base + 8192)  = *(uint4*)lo;
    }
}

// ---------------- pack gate/up interleaved B tiles (8-col groups alternate) ----------------
__global__ void pack_gu(const float* __restrict__ gate_w, const float* __restrict__ up_w,
                        uint8_t* __restrict__ dst, int nChunks)
{
    for (int id = blockIdx.x * blockDim.x + threadIdx.x; id < nChunks;
         id += gridDim.x * blockDim.x) {
        const int tile = id >> 9;
        const int w = id & 511;
        const int r = w >> 2, c = w & 3;
        const int jt = tile >> 6;
        const int s  = tile & 63;
        const int g = r >> 3, i = r & 7;
        const int lcol = jt * 64 + (g >> 1) * 8 + i;
        const float* src = (g & 1) ? up_w : gate_w;
        const float* p = src + (size_t)lcol * 2048 + s * 32 + c * 8;
        float v[8];
        *(float4*)&v[0] = *(const float4*)p;
        *(float4*)&v[4] = *(const float4*)(p + 4);
        uint32_t hi[4], lo[4];
        cvt8u(v, hi, lo);
        uint8_t* base = dst + (size_t)tile * 16384 + swz(r, c);
        *(uint4*)base           = *(uint4*)hi;
        *(uint4*)(base + 8192)  = *(uint4*)lo;
    }
}

// ---------------- fused RMSNorm (optionally * mask) -> packed A tiles ----------------
__global__ __launch_bounds__(256) void rmsnorm_pack(const float* __restrict__ x,
                                                    const float* __restrict__ w,
                                                    const float* __restrict__ mask,
                                                    uint8_t* __restrict__ dst)
{
    const int m = blockIdx.x;
    const int t = threadIdx.x;
    const float* row = x + (size_t)m * DMODEL;
    float v[8];
    *(float4*)&v[0] = *(const float4*)(row + t * 8);
    *(float4*)&v[4] = *(const float4*)(row + t * 8 + 4);
    float s = 0.f;
#pragma unroll
    for (int j = 0; j < 8; j++) s += v[j] * v[j];
#pragma unroll
    for (int o = 16; o > 0; o >>= 1) s += __shfl_xor_sync(0xffffffffu, s, o);
    __shared__ float red[8];
    const int lane = t & 31, wid = t >> 5;
    if (lane == 0) red[wid] = s;
    __syncthreads();
    if (wid == 0) {
        s = (lane < 8) ? red[lane] : 0.f;
#pragma unroll
        for (int o = 4; o > 0; o >>= 1) s += __shfl_xor_sync(0xffffffffu, s, o);
        if (lane == 0) red[0] = s;
    }
    __syncthreads();
    const float inv = rsqrtf(red[0] * (1.0f / (float)DMODEL) + 1e-6f) *
                      (mask ? mask[m] : 1.f);
    float wv[8];
    *(float4*)&wv[0] = *(const float4*)(w + t * 8);
    *(float4*)&wv[4] = *(const float4*)(w + t * 8 + 4);
#pragma unroll
    for (int j = 0; j < 8; j++) v[j] = v[j] * inv * wv[j];
    uint32_t hi[4], lo[4];
    cvt8u(v, hi, lo);
    const int st = t >> 2, c = t & 3, r = m & 127;
    uint8_t* base = dst + (size_t)((m >> 7) * 64 + st) * 16384 + swz(r, c);
    *(uint4*)base          = *(uint4*)hi;
    *(uint4*)(base + 8192) = *(uint4*)lo;
}

// ====== shared GEMM mainloop (3-stage K32 cp.async, bf16x3) ======
// Term-outermost MMA ordering: per mt, three passes (hh, lh, hl) over nt so
// consecutive MMAs hit different accumulators (RAW distance 4, not 1).
#define OFF_AL 8192
#define OFF_BH 16384
#define OFF_BL 24576
#define STG    32768
#define GSMEM  (3*STG)

#define GEMM_MAINLOOP()                                                            \
    extern __shared__ char sm[];                                                   \
    const int tid  = threadIdx.x;                                                  \
    const int warp = tid >> 5, lane = tid & 31;                                    \
    const int wm = warp >> 2, wn = warp & 3;                                       \
    const uint32_t sbase = smem_u32(sm);                                           \
    const uint8_t* aT = Ap + (size_t)blockIdx.x * nslab * 16384;                   \
    const uint8_t* bT = Bp + (size_t)blockIdx.y * nslab * 16384;                   \
    float acc[4][4][4];                                                            \
    _Pragma("unroll") for (int i = 0; i < 4; i++)                                  \
    _Pragma("unroll") for (int j = 0; j < 4; j++)                                  \
    _Pragma("unroll") for (int r = 0; r < 4; r++) acc[i][j][r] = 0.f;              \
    _Pragma("unroll")                                                              \
    for (int ss = 0; ss < 2; ss++) {                                               \
        const uint32_t d = sbase + (uint32_t)ss * STG;                             \
        const size_t o = (size_t)ss * 16384;                                       \
        _Pragma("unroll")                                                          \
        for (int j = 0; j < 4; j++) {                                              \
            const uint32_t cid = (uint32_t)tid * 16 + (uint32_t)j * 4096;          \
            CPASYNC16(d + cid,         aT + o + cid);                              \
            CPASYNC16(d + 16384 + cid, bT + o + cid);                              \
        }                                                                          \
        asm volatile("cp.async.commit_group;" ::: "memory");                      \
    }                                                                              \
    const int lrow  = lane & 15;                                                   \
    const int lcsel = lane >> 4;                                                   \
    int cur = 0;                                                                   \
    for (int s = 0; s < nslab; s++) {                                              \
        if (s + 1 < nslab) { asm volatile("cp.async.wait_group 1;" ::: "memory"); }\
        else               { asm volatile("cp.async.wait_group 0;" ::: "memory"); }\
        __syncthreads();                                                           \
        if (s + 2 < nslab) {                                                       \
            int nx2 = cur + 2; if (nx2 >= 3) nx2 -= 3;                             \
            const uint32_t d = sbase + (uint32_t)nx2 * STG;                        \
            const size_t o = (size_t)(s + 2) * 16384;                              \
            _Pragma("unroll")                                                      \
            for (int j = 0; j < 4; j++) {                                          \
                const uint32_t cid = (uint32_t)tid * 16 + (uint32_t)j * 4096;      \
                CPASYNC16(d + cid,         aT + o + cid);                          \
                CPASYNC16(d + 16384 + cid, bT + o + cid);                          \
            }                                                                      \
            asm volatile("cp.async.commit_group;" ::: "memory");                  \
        }                                                                          \
        const uint32_t stb = sbase + (uint32_t)cur * STG;                          \
        _Pragma("unroll")                                                          \
        for (int ks = 0; ks < 2; ks++) {                                           \
            const int kc = ks * 2 + lcsel;                                         \
            uint32_t bh[2][4], bl[2][4];                                           \
            _Pragma("unroll")                                                      \
            for (int bt = 0; bt < 2; bt++) {                                       \
                const uint32_t off = swz(wn*32 + bt*16 + lrow, kc);                \
                LDSM_X4(bh[bt], stb + OFF_BH + off);                               \
                LDSM_X4(bl[bt], stb + OFF_BL + off);                               \
            }                                                                      \
            _Pragma("unroll")                                                      \
            for (int mt = 0; mt < 4; mt++) {                                       \
                uint32_t ah[4], al[4];                                             \
                const uint32_t off = swz(wm*64 + mt*16 + lrow, kc);                \
                LDSM_X4(ah, stb + off);                                            \
                LDSM_X4(al, stb + OFF_AL + off);                                   \
                _Pragma("unroll")                                                  \
                for (int nt = 0; nt < 4; nt++) {                                   \
                    const int bt = nt >> 1, sel = nt & 1;                          \
                    MMA16816(acc[mt][nt], ah, bh[bt][sel], bh[bt][2+sel]);         \
                }                                                                  \
                _Pragma("unroll")                                                  \
                for (int nt = 0; nt < 4; nt++) {                                   \
                    const int bt = nt >> 1, sel = nt & 1;                          \
                    MMA16816(acc[mt][nt], al, bh[bt][sel], bh[bt][2+sel]);         \
                }                                                                  \
                _Pragma("unroll")                                                  \
                for (int nt = 0; nt < 4; nt++) {                                   \
                    const int bt = nt >> 1, sel = nt & 1;                          \
                    MMA16816(acc[mt][nt], ah, bl[bt][sel], bl[bt][2+sel]);         \
                }                                                                  \
            }                                                                      \
        }                                                                          \
        if (++cur == 3) cur = 0;                                                   \
    }

__global__ __launch_bounds__(256, 2) void gemm_mma(
    const uint8_t* __restrict__ Ap, const uint8_t* __restrict__ Bp,
    float* __restrict__ C, const float* __restrict__ addv,
    int N, int nslab, int addflag)
{
    GEMM_MAINLOOP()
    const int g  = lane >> 2;
    const int t4 = lane & 3;
    const int bm = blockIdx.x * 128, bn = blockIdx.y * 128;
#pragma unroll
    for (int mt = 0; mt < 4; mt++) {
        const int row = bm + wm*64 + mt*16 + g;
#pragma unroll
        for (int nt = 0; nt < 4; nt++) {
            const int col = bn + wn*32 + nt*8 + t4*2;
            if (col < N) {
                float2 v0 = make_float2(acc[mt][nt][0], acc[mt][nt][1]);
                float2 v1 = make_float2(acc[mt][nt][2], acc[mt][nt][3]);
                const size_t i0 = (size_t)row * N + col;
                const size_t i1 = (size_t)(row + 8) * N + col;
                if (addflag) {
                    const float2 a0 = *(const float2*)(addv + i0);
                    const float2 a1 = *(const float2*)(addv + i1);
                    v0.x += a0.x; v0.y += a0.y; v1.x += a1.x; v1.y += a1.y;
                }
                *(float2*)(C + i0) = v0;
                *(float2*)(C + i1) = v1;
            }
        }
    }
}

// gate/up GEMM with fused silu(g)*u epilogue writing packed bf16 hi/lo A tiles
__global__ __launch_bounds__(256, 2) void gemm_mma_silu(
    const uint8_t* __restrict__ Ap, const uint8_t* __restrict__ Bp,
    uint8_t* __restrict__ paOut, int nslab)
{
    GEMM_MAINLOOP()
    const int g  = lane >> 2;
    const int t4 = lane & 3;
    const int bm = blockIdx.x * 128;
#pragma unroll
    for (int mt = 0; mt < 4; mt++) {
        const int r0 = bm + wm*64 + mt*16 + g;
#pragma unroll
        for (int ntp = 0; ntp < 2; ntp++) {
            const float* ga = acc[mt][2*ntp];
            const float* ua = acc[mt][2*ntp + 1];
            const int L = blockIdx.y * 64 + (wn*2 + ntp) * 8 + t4 * 2;
            const int c16 = (L >> 3) & 3;
            const int ib = (L & 7) * 2;
#pragma unroll
            for (int rr = 0; rr < 2; rr++) {
                const int row = r0 + rr * 8;
                const float g0 = ga[2*rr], g1 = ga[2*rr + 1];
                const float v0 = ua[2*rr]     * g0 / (1.f + expf(-g0));
                const float v1 = ua[2*rr + 1] * g1 / (1.f + expf(-g1));
                __nv_bfloat162 h = __float22bfloat162_rn(make_float2(v0, v1));
                const float h0 = __bfloat162float(h.x), h1 = __bfloat162float(h.y);
                __nv_bfloat162 l = __float22bfloat162_rn(make_float2(v0 - h0, v1 - h1));
                uint8_t* base = paOut + ((size_t)(row >> 7) * 172 + (L >> 5)) * 16384
                                + swz(row & 127, c16) + ib;
                *(uint32_t*)base          = *(uint32_t*)&h;
                *(uint32_t*)(base + 8192) = *(uint32_t*)&l;
            }
        }
    }
}

// ---------------- causal depthwise conv1d (float4 over channels) ----------------
__global__ void conv_kernel(const float* __restrict__ zx,
                            const float* __restrict__ cw,
                            const float* __restrict__ cb,
                            float* __restrict__ xbc)
{
    const int m = blockIdx.x;
    const int t = m & (SEQ - 1);
#pragma unroll
    for (int it = 0; it < CONVDIM / 4 / 256; it++) {
        const int c = (it * 256 + threadIdx.x) * 4;
        float4 acc = *(const float4*)(cb + c);
        const float4 w0 = *(const float4*)(cw + (size_t)(c + 0) * 4);
        const float4 w1 = *(const float4*)(cw + (size_t)(c + 1) * 4);
        const float4 w2 = *(const float4*)(cw + (size_t)(c + 2) * 4);
        const float4 w3 = *(const float4*)(cw + (size_t)(c + 3) * 4);
#pragma unroll
        for (int j = 0; j < 4; j++) {
            const int tt = t - 3 + j;
            if (tt >= 0) {
                const float4 v = *(const float4*)(zx + (size_t)(m - 3 + j) * DPROJ + DINNER + c);
                acc.x = fmaf((&w0.x)[j], v.x, acc.x);
                acc.y = fmaf((&w1.x)[j], v.y, acc.y);
                acc.z = fmaf((&w2.x)[j], v.z, acc.z);
                acc.w = fmaf((&w3.x)[j], v.w, acc.w);
            }
        }
        *(float4*)(xbc + (size_t)m * CONVDIM + c) = acc;
    }
}

// ---------------- SSM scan, p-split x4: 4 blocks per (b,h), 16 p-rows each ----------------
#define CHK 8
#define SBUF 2064
__global__ __launch_bounds__(256) void scan_kernel(
    const float* __restrict__ xbc, const float* __restrict__ zx,
    const float* __restrict__ Dv, const float* __restrict__ zb,
    float* __restrict__ gated)
{
    const int blk = blockIdx.x;          // 0..255
    const int bh = blk >> 2;
    const int b = bh >> 5;
    const int h = bh & 31;
    const int quarter = blk & 3;
    const int tid = threadIdx.x;
    const int p = quarter * 16 + (tid >> 4);
    const int q = tid & 15;
    const int n0 = q << 2;

    __shared__ __align__(16) float sd[2][SBUF];

    int lts[9], loff[9], lkind[9], lsh[9];
    bool lvalid[9];
#pragma unroll
    for (int k = 0; k < 9; k++) {
        const int e = tid + k * 256;
        lvalid[k] = (e < CHK * 257);
        const int tsub = e / 257;
        const int j = e - tsub * 257;
        lts[k] = tsub;
        if (j < 64)        { lkind[k] = 0; loff[k] = h * HEADDIM + j;                     lsh[k] = tsub*64 + j; }
        else if (j < 128)  { lkind[k] = 0; loff[k] = DINNER + h * DSTATE + (j - 64);      lsh[k] = 512 + tsub*64 + (j-64); }
        else if (j < 192)  { lkind[k] = 0; loff[k] = DINNER + NHEADS*DSTATE + h*DSTATE + (j-128); lsh[k] = 1024 + tsub*64 + (j-128); }
        else if (j < 256)  { lkind[k] = 1; loff[k] = h * HEADDIM + (j - 192);             lsh[k] = 1536 + tsub*64 + (j-192); }
        else               { lkind[k] = 2; loff[k] = 2*DINNER + 2*NHEADS*DSTATE + h;      lsh[k] = 2048 + tsub; }
    }
#pragma unroll
    for (int k = 0; k < 9; k++) {
        if (lvalid[k]) {
            const size_t m = (size_t)b * SEQ + lts[k];
            float v;
            if (lkind[k] == 0) v = xbc[m * CONVDIM + loff[k]];
            else               v = zx[m * DPROJ + loff[k]];
            if (lkind[k] == 2) v = 1.f / (1.f + expf(v));
            sd[0][lsh[k]] = v;
        }
    }
    __syncthreads();

    float st[4];
#pragma unroll
    for (int i = 0; i < 4; i++) st[i] = 0.f;
    const float Dh = Dv[h];
    const float zbias = zb[h * HEADDIM + p];

    const int NC = SEQ / CHK;
    for (int c = 0; c < NC; c++) {
        const int cur = c & 1;
        const bool pre = (c + 1 < NC);
        float regv[9];
        if (pre) {
#pragma unroll
            for (int k = 0; k < 9; k++) {
                if (lvalid[k]) {
                    const size_t m = (size_t)b * SEQ + (c + 1) * CHK + lts[k];
                    float v;
                    if (lkind[k] == 0) v = xbc[m * CONVDIM + loff[k]];
                    else               v = zx[m * DPROJ + loff[k]];
                    if (lkind[k] == 2) v = 1.f / (1.f + expf(v));
                    regv[k] = v;
                }
            }
        }
        const float* sb = sd[cur];
#pragma unroll
        for (int tsub = 0; tsub < CHK; tsub++) {
            const float a  = sb[2048 + tsub];
            const float xv = sb[tsub*64 + p];
            float Bv[4], Cv[4];
            *(float4*)&Bv[0] = *(const float4*)(sb + 512 + tsub*64 + n0);
            *(float4*)&Cv[0] = *(const float4*)(sb + 1024 + tsub*64 + n0);
            float y = 0.f;
#pragma unroll
            for (int i = 0; i < 4; i++) {
                st[i] = a * st[i] + xv * Bv[i];
                y = fmaf(st[i], Cv[i], y);
            }
            y += __shfl_xor_sync(0xffffffffu, y, 1);
            y += __shfl_xor_sync(0xffffffffu, y, 2);
            y += __shfl_xor_sync(0xffffffffu, y, 4);
            y += __shfl_xor_sync(0xffffffffu, y, 8);
            if (q == 0) {
                const size_t m = (size_t)b * SEQ + c * CHK + tsub;
                const float zval = sb[1536 + tsub*64 + p] + zbias;
                const float sig = 1.f / (1.f + expf(-zval));
                gated[m * DMODEL + h * HEADDIM + p] = (y + Dh * xv) * (zval * sig);
            }
        }
        if (pre) {
#pragma unroll
            for (int k = 0; k < 9; k++)
                if (lvalid[k]) sd[cur ^ 1][lsh[k]] = regv[k];
        }
        __syncthreads();
    }
}

// ---------------- launcher ----------------
extern "C" void kernel_launch(void* const* d_in, const int* in_sizes, int n_in,
                              void* d_out, int out_size)
{
    (void)in_sizes; (void)n_in; (void)out_size;
    const float* hidden     = (const float*)d_in[0];
    const float* mask       = (const float*)d_in[1];
    const float* in_proj_w  = (const float*)d_in[2];
    const float* conv_w     = (const float*)d_in[3];
    const float* conv_b     = (const float*)d_in[4];
    const float* z_bias     = (const float*)d_in[5];
    const float* Dv         = (const float*)d_in[6];
    const float* out_proj_w = (const float*)d_in[7];
    const float* ln1_w      = (const float*)d_in[8];
    const float* ln2_w      = (const float*)d_in[9];
    const float* gate_w     = (const float*)d_in[10];
    const float* up_w       = (const float*)d_in[11];
    const float* down_w     = (const float*)d_in[12];
    float* out = (float*)d_out;

    float *zx, *xbc, *gated, *res2;
    uint8_t *pa, *pa2, *pb;
    cudaGetSymbolAddress((void**)&zx,    g_zx);
    cudaGetSymbolAddress((void**)&xbc,   g_xbc);
    cudaGetSymbolAddress((void**)&gated, g_gated);
    cudaGetSymbolAddress((void**)&res2,  g_res2);
    cudaGetSymbolAddress((void**)&pa,    g_pa);
    cudaGetSymbolAddress((void**)&pa2,   g_pa2);
    cudaGetSymbolAddress((void**)&pb,    g_pb);

    uint8_t* pbI  = pb + (size_t)PB_I * 16384;
    uint8_t* pbO  = pb + (size_t)PB_O * 16384;
    uint8_t* pbGU = pb + (size_t)PB_GU * 16384;
    uint8_t* pbD  = pb + (size_t)PB_D * 16384;

    cudaFuncSetAttribute(gemm_mma, cudaFuncAttributeMaxDynamicSharedMemorySize, GSMEM);
    cudaFuncSetAttribute(gemm_mma_silu, cudaFuncAttributeMaxDynamicSharedMemorySize, GSMEM);
    const int PKG = 4096;

    cudaStream_t s2;
    cudaStreamCreateWithFlags(&s2, cudaStreamNonBlocking);
    cudaEvent_t evF, evI, evO, evGU, evD;
    cudaEventCreateWithFlags(&evF,  cudaEventDisableTiming);
    cudaEventCreateWithFlags(&evI,  cudaEventDisableTiming);
    cudaEventCreateWithFlags(&evO,  cudaEventDisableTiming);
    cudaEventCreateWithFlags(&evGU, cudaEventDisableTiming);
    cudaEventCreateWithFlags(&evD,  cudaEventDisableTiming);

    cudaEventRecord(evF, 0);
    cudaStreamWaitEvent(s2, evF, 0);
    pack_tiles<<<PKG, 256, 0, s2>>>(in_proj_w, pbI, 2048, 64, DPROJ, 65*64*512);
    cudaEventRecord(evI, s2);
    pack_tiles<<<PKG, 256, 0, s2>>>(out_proj_w, pbO, 2048, 64, DMODEL, 16*64*512);
    cudaEventRecord(evO, s2);
    pack_gu<<<PKG, 256, 0, s2>>>(gate_w, up_w, pbGU, 86*64*512);
    cudaEventRecord(evGU, s2);
    pack_tiles<<<PKG, 256, 0, s2>>>(down_w, pbD, 5504, 172, DMODEL, 16*172*512);
    cudaEventRecord(evD, s2);

    // ---- main chain ----
    rmsnorm_pack<<<MROWS, 256>>>(hidden, ln1_w, mask, pa);
    cudaStreamWaitEvent(0, evI, 0);
    gemm_mma<<<dim3(32, 65), 256, GSMEM>>>(pa, pbI, zx, nullptr, DPROJ, 64, 0);

    conv_kernel<<<MROWS, 256>>>(zx, conv_w, conv_b, xbc);
    scan_kernel<<<4 * BATCH * NHEADS, 256>>>(xbc, zx, Dv, z_bias, gated);

    pack_tiles<<<PKG, 256>>>(gated, pa, 2048, 64, MROWS, 32*64*512);
    cudaStreamWaitEvent(0, evO, 0);
    gemm_mma<<<dim3(32, 16), 256, GSMEM>>>(pa, pbO, res2, hidden, DMODEL, 64, 1);

    // ---- MLP ----
    rmsnorm_pack<<<MROWS, 256>>>(res2, ln2_w, nullptr, pa);
    cudaStreamWaitEvent(0, evGU, 0);
    gemm_mma_silu<<<dim3(32, 86), 256, GSMEM>>>(pa, pbGU, pa2, 64);

    cudaStreamWaitEvent(0, evD, 0);
    gemm_mma<<<dim3(32, 16), 256, GSMEM>>>(pa2, pbD, out, res2, DMODEL, 172, 1);
}